// round 12
// baseline (speedup 1.0000x reference)
#include <cuda_runtime.h>
#include <cstdint>
#include <cstring>
#include <vector>
#include <algorithm>

namespace {
constexpr int kN = 8192, kD = 512, kNC = 64, kNR = 5, kRC = kNC * kNR;
constexpr int kTK = 16, kIters = 20;
constexpr int kCH = 32, kCHP = kN / kCH;   // 32 chunks x 256 points
constexpr int kCand = 32;                  // topk candidate count

// ---------------- host-side JAX threefry2x32 ----------------
struct U2 { uint32_t a, b; };
static inline uint32_t rotl32(uint32_t v, int r) { return (v << r) | (v >> (32 - r)); }

static U2 threefry(U2 key, uint32_t x0, uint32_t x1) {
    uint32_t ks0 = key.a, ks1 = key.b, ks2 = key.a ^ key.b ^ 0x1BD11BDAu;
    const int ra[4] = {13, 15, 26, 6}, rb[4] = {17, 29, 16, 24};
    x0 += ks0; x1 += ks1;
    for (int i = 0; i < 4; i++) { x0 += x1; x1 = rotl32(x1, ra[i]); x1 ^= x0; }
    x0 += ks1; x1 += ks2 + 1u;
    for (int i = 0; i < 4; i++) { x0 += x1; x1 = rotl32(x1, rb[i]); x1 ^= x0; }
    x0 += ks2; x1 += ks0 + 2u;
    for (int i = 0; i < 4; i++) { x0 += x1; x1 = rotl32(x1, ra[i]); x1 ^= x0; }
    x0 += ks0; x1 += ks1 + 3u;
    for (int i = 0; i < 4; i++) { x0 += x1; x1 = rotl32(x1, rb[i]); x1 ^= x0; }
    x0 += ks1; x1 += ks2 + 4u;
    for (int i = 0; i < 4; i++) { x0 += x1; x1 = rotl32(x1, ra[i]); x1 ^= x0; }
    x0 += ks2; x1 += ks0 + 5u;
    return {x0, x1};
}

constexpr bool kPartitionable = true;

static void split_keys(U2 key, int n, U2* out) {
    if (kPartitionable) {
        for (int i = 0; i < n; i++) out[i] = threefry(key, 0u, (uint32_t)i);
    } else {
        std::vector<uint32_t> o(2 * n);
        for (int i = 0; i < n; i++) {
            U2 y = threefry(key, (uint32_t)i, (uint32_t)(n + i));
            o[i] = y.a; o[n + i] = y.b;
        }
        for (int j = 0; j < n; j++) out[j] = { o[2 * j], o[2 * j + 1] };
    }
}

static void random_bits32(U2 key, int n, uint32_t* bits) {
    if (kPartitionable) {
        for (int i = 0; i < n; i++) {
            U2 y = threefry(key, 0u, (uint32_t)i);
            bits[i] = y.a ^ y.b;
        }
    } else {
        int h = n / 2;
        for (int i = 0; i < h; i++) {
            U2 y = threefry(key, (uint32_t)i, (uint32_t)(h + i));
            bits[i] = y.a; bits[h + i] = y.b;
        }
    }
}

static void compute_init_indices(int out_idx[kRC]) {
    U2 master{0u, 1234u};
    U2 runkeys[kNR];
    split_keys(master, kNR, runkeys);
    std::vector<int> val(kN), tmp(kN);
    std::vector<uint64_t> kv(kN);
    std::vector<uint32_t> bits(kN);
    for (int r = 0; r < kNR; r++) {
        for (int i = 0; i < kN; i++) val[i] = i;
        U2 cur = runkeys[r];
        for (int round = 0; round < 2; round++) {
            U2 nk[2];
            split_keys(cur, 2, nk);
            cur = nk[0];
            random_bits32(nk[1], kN, bits.data());
            for (int i = 0; i < kN; i++)
                kv[i] = ((uint64_t)bits[i] << 32) | (uint32_t)i;
            std::sort(kv.begin(), kv.end());
            for (int i = 0; i < kN; i++) tmp[i] = val[(uint32_t)(kv[i] & 0xffffffffu)];
            val.swap(tmp);
        }
        for (int c = 0; c < kNC; c++) out_idx[r * kNC + c] = val[c];
    }
}
} // namespace

// ---------------- device scratch ----------------
__device__ float g_cent[kRC * kD];
__device__ float g_cnorm[kRC];
__device__ int   g_labels[kNR * kN];
__device__ int   g_flags[kNR * kN];
__device__ int   g_knn[kN * kTK];
__device__ int   g_cand[kN * kCand];
__device__ float g_part[(size_t)kNR * kCH * kNC * kD];
__device__ int   g_pcnt[kNR * kCH * kNC];
__device__ float g_Ahi[(size_t)kN * kD];   // student hi (tf32)
__device__ float g_Bhi[(size_t)kN * kD];   // teacher hi (tf32)
__device__ float g_Chi[(size_t)kRC * kD];  // centroid hi (tf32)

struct IdxArr { int v[kRC]; };

// ---------------- tf32 helpers ----------------
__device__ __forceinline__ float tf32r(float x) {
    uint32_t u; asm("cvt.rna.tf32.f32 %0,%1;" : "=r"(u) : "f"(x));
    return __uint_as_float(u);
}

#define MMA_TF32(d, a, b0, b1) \
    asm volatile( \
        "mma.sync.aligned.m16n8k8.row.col.f32.tf32.tf32.f32 " \
        "{%0,%1,%2,%3}, {%4,%5,%6,%7}, {%8,%9}, {%0,%1,%2,%3};" \
        : "+f"((d)[0]), "+f"((d)[1]), "+f"((d)[2]), "+f"((d)[3]) \
        : "r"((a)[0]), "r"((a)[1]), "r"((a)[2]), "r"((a)[3]), \
          "r"(b0), "r"(b1))

#define CP_ASYNC16(dst, src) \
    asm volatile("cp.async.cg.shared.global [%0], [%1], 16;" :: "r"(dst), "l"(src) : "memory")
#define CP_COMMIT() asm volatile("cp.async.commit_group;" ::: "memory")
#define CP_WAIT1()  asm volatile("cp.async.wait_group 1;" ::: "memory")
#define CP_WAIT0()  asm volatile("cp.async.wait_group 0;" ::: "memory")

namespace {
constexpr int kPitch = 36;
constexpr int kATileB = 128 * kPitch * 4;   // 18432
constexpr int kBTileB = 64 * kPitch * 4;    // 9216
constexpr int kChunks = kD / 32;            // 16
constexpr int kGemmBufB = 2 * kATileB;              // Ahi + Bhi (both 128 rows)
constexpr int kAsgBufB  = kATileB + kBTileB;        // Ahi(128) + Chi(64)
}

// ---------------- kernel 0: fp32 -> tf32 hi (inputs) ----------------
__global__ void __launch_bounds__(256) split_hi_kernel(const float* __restrict__ A,
                                                       const float* __restrict__ B)
{
    size_t i = ((size_t)blockIdx.x * 256 + threadIdx.x) * 4;
    float4 a = *reinterpret_cast<const float4*>(A + i);
    float4 b = *reinterpret_cast<const float4*>(B + i);
    float4 ah, bh;
    ah.x = tf32r(a.x); ah.y = tf32r(a.y); ah.z = tf32r(a.z); ah.w = tf32r(a.w);
    bh.x = tf32r(b.x); bh.y = tf32r(b.y); bh.z = tf32r(b.z); bh.w = tf32r(b.w);
    *reinterpret_cast<float4*>(g_Ahi + i) = ah;
    *reinterpret_cast<float4*>(g_Bhi + i) = bh;
}

__global__ void __launch_bounds__(256) split_cent_hi_kernel()
{
    size_t i = ((size_t)blockIdx.x * 256 + threadIdx.x) * 4;
    float4 c = *reinterpret_cast<const float4*>(g_cent + i);
    float4 ch;
    ch.x = tf32r(c.x); ch.y = tf32r(c.y); ch.z = tf32r(c.z); ch.w = tf32r(c.w);
    *reinterpret_cast<float4*>(g_Chi + i) = ch;
}

// ---------------- kernel 1: sim GEMM, hi-only tf32 ----------------
__global__ void __launch_bounds__(256) gemm_hi_kernel(float* __restrict__ C)
{
    extern __shared__ char smem[];
    const int tid = threadIdx.x;
    const int lane = tid & 31, wid = tid >> 5;
    const int wm = wid & 3, wn = wid >> 2;
    const int gm = lane >> 2, gk = lane & 3;
    const int n0 = blockIdx.x * 128, m0 = blockIdx.y * 128;
    const uint32_t sbase = (uint32_t)__cvta_generic_to_shared(smem);

    float acc[2][8][4];
#pragma unroll
    for (int mt = 0; mt < 2; mt++)
#pragma unroll
        for (int nt = 0; nt < 8; nt++)
#pragma unroll
            for (int q = 0; q < 4; q++) acc[mt][nt][q] = 0.f;

    auto copy_chunk = [&](int c, int buf) {
        const int koff = c * 32;
        const uint32_t tb = sbase + (uint32_t)buf * kGemmBufB;
#pragma unroll
        for (int q = 0; q < 4; q++) {
            const int idx = q * 256 + tid;
            const int row = idx >> 3, f4 = idx & 7;
            const uint32_t doff = (uint32_t)(row * kPitch + f4 * 4) * 4;
            CP_ASYNC16(tb + doff, g_Ahi + (size_t)(m0 + row) * kD + koff + f4 * 4);
            CP_ASYNC16(tb + kATileB + doff, g_Bhi + (size_t)(n0 + row) * kD + koff + f4 * 4);
        }
        CP_COMMIT();
    };

    copy_chunk(0, 0);
    copy_chunk(1, 1);

    for (int c = 0; c < kChunks; c++) {
        if (c < kChunks - 1) { CP_WAIT1(); } else { CP_WAIT0(); }
        __syncthreads();
        const int buf = c & 1;
        const float* Ah = reinterpret_cast<const float*>(smem + (size_t)buf * kGemmBufB);
        const float* Bh = reinterpret_cast<const float*>(smem + (size_t)buf * kGemmBufB + kATileB);

#pragma unroll
        for (int kk = 0; kk < 4; kk++) {
            const int kb = kk * 8 + gk;
            uint32_t ah[2][4];
#pragma unroll
            for (int mt = 0; mt < 2; mt++) {
                const int r0 = wm * 32 + mt * 16 + gm;
                ah[mt][0] = __float_as_uint(Ah[r0 * kPitch + kb]);
                ah[mt][1] = __float_as_uint(Ah[(r0 + 8) * kPitch + kb]);
                ah[mt][2] = __float_as_uint(Ah[r0 * kPitch + kb + 4]);
                ah[mt][3] = __float_as_uint(Ah[(r0 + 8) * kPitch + kb + 4]);
            }
#pragma unroll
            for (int nt = 0; nt < 8; nt++) {
                const int rB = wn * 64 + nt * 8 + gm;
                uint32_t bh0 = __float_as_uint(Bh[rB * kPitch + kb]);
                uint32_t bh1 = __float_as_uint(Bh[rB * kPitch + kb + 4]);
                MMA_TF32(acc[0][nt], ah[0], bh0, bh1);
                MMA_TF32(acc[1][nt], ah[1], bh0, bh1);
            }
        }
        __syncthreads();
        if (c + 2 < kChunks) copy_chunk(c + 2, (c + 2) & 1);
    }

#pragma unroll
    for (int mt = 0; mt < 2; mt++) {
#pragma unroll
        for (int nt = 0; nt < 8; nt++) {
            const int r0 = m0 + wm * 32 + mt * 16 + gm;
            const int r1 = r0 + 8;
            const int col = n0 + wn * 64 + nt * 8 + 2 * gk;
            float2 v0, v1;
            v0.x = acc[mt][nt][0] + ((r0 == col) ? 10.f : 0.f);
            v0.y = acc[mt][nt][1] + ((r0 == col + 1) ? 10.f : 0.f);
            v1.x = acc[mt][nt][2] + ((r1 == col) ? 10.f : 0.f);
            v1.y = acc[mt][nt][3] + ((r1 == col + 1) ? 10.f : 0.f);
            *reinterpret_cast<float2*>(&C[(size_t)r0 * kN + col]) = v0;
            *reinterpret_cast<float2*>(&C[(size_t)r1 * kN + col]) = v1;
        }
    }
}

// ---------------- kernel 2: per-row top-32 candidates (tf32 values) ----------
__device__ __forceinline__ bool beats(float v1, int i1, float v2, int i2) {
    return (v1 > v2) || (v1 == v2 && i1 < i2);
}

__global__ void __launch_bounds__(256) topk32_kernel(const float* __restrict__ sim)
{
    extern __shared__ char smem[];
    float* sv = reinterpret_cast<float*>(smem);                 // [256][32]
    int*   si = reinterpret_cast<int*>(sv + 256 * kCand);       // [256][32]
    const int row = blockIdx.x, t = threadIdx.x;
    float tv[kCand]; int ti[kCand];
#pragma unroll
    for (int k = 0; k < kCand; k++) { tv[k] = -3.402823466e38f; ti[k] = 0x7fffffff; }

    const float* rp = sim + (size_t)row * kN;
    for (int j = t; j < kN; j += 256) {
        float v = rp[j];
        if (beats(v, j, tv[kCand - 1], ti[kCand - 1])) {
            float cv = v; int ci = j;
#pragma unroll
            for (int k = 0; k < kCand; k++) {
                if (beats(cv, ci, tv[k], ti[k])) {
                    float fv = tv[k]; int fi = ti[k];
                    tv[k] = cv; ti[k] = ci; cv = fv; ci = fi;
                }
            }
        }
    }
#pragma unroll
    for (int k = 0; k < kCand; k++) { sv[t * kCand + k] = tv[k]; si[t * kCand + k] = ti[k]; }
    __syncthreads();

    for (int s = 128; s >= 1; s >>= 1) {
        if (t < s) {
            float mv[kCand]; int mi[kCand];
            int ia = 0, ib = 0;
#pragma unroll
            for (int k = 0; k < kCand; k++) {
                float av = sv[t * kCand + ia], bw = sv[(t + s) * kCand + ib];
                int   ai = si[t * kCand + ia], bj = si[(t + s) * kCand + ib];
                bool ta = beats(av, ai, bw, bj);
                mv[k] = ta ? av : bw; mi[k] = ta ? ai : bj;
                if (ta) ia++; else ib++;
            }
#pragma unroll
            for (int k = 0; k < kCand; k++) { sv[t * kCand + k] = mv[k]; si[t * kCand + k] = mi[k]; }
        }
        __syncthreads();
    }
    if (t < kCand) g_cand[row * kCand + t] = si[t];
}

// ---------------- kernel 2b: fp32 rescore of candidates -> exact top-16 ------
__global__ void __launch_bounds__(256) rescore_kernel(const float* __restrict__ S,
                                                      const float* __restrict__ T)
{
    __shared__ float cv[kCand];
    __shared__ int   ci[kCand];
    const int row = blockIdx.x;
    const int tid = threadIdx.x;
    const int wid = tid >> 5, lane = tid & 31;

#pragma unroll
    for (int k = 0; k < 4; k++) {
        const int slot = wid + 8 * k;
        const int cand = g_cand[row * kCand + slot];
        float s = 0.f;
#pragma unroll
        for (int u = 0; u < 16; u++)
            s = fmaf(S[(size_t)row * kD + u * 32 + lane],
                     T[(size_t)cand * kD + u * 32 + lane], s);
#pragma unroll
        for (int m = 16; m >= 1; m >>= 1) s += __shfl_xor_sync(0xffffffffu, s, m);
        if (lane == 0) {
            if (cand == row) s += 10.f;
            cv[slot] = s; ci[slot] = cand;
        }
    }
    __syncthreads();
    if (tid == 0) {
        unsigned used = 0;
        for (int k = 0; k < kTK; k++) {
            float bv = -3.402823466e38f; int bi = 0x7fffffff, bs = -1;
            for (int q = 0; q < kCand; q++) {
                if (used & (1u << q)) continue;
                if (beats(cv[q], ci[q], bv, bi)) { bv = cv[q]; bi = ci[q]; bs = q; }
            }
            used |= (1u << bs);
            g_knn[row * kTK + k] = bi;
        }
    }
}

// ---------------- kernel 3/4: gather + norms ----------------
__global__ void gather_kernel(const float* __restrict__ X, IdxArr ia)
{
    int b = blockIdx.x;
    int src = ia.v[b];
    for (int d = threadIdx.x; d < kD; d += blockDim.x)
        g_cent[(size_t)b * kD + d] = X[(size_t)src * kD + d];
}

__global__ void __launch_bounds__(128) cnorm_kernel()
{
    int rc = blockIdx.x;
    float s = 0.f;
    for (int d = threadIdx.x; d < kD; d += 128) {
        float v = g_cent[(size_t)rc * kD + d];
        s = fmaf(v, v, s);
    }
#pragma unroll
    for (int m = 16; m >= 1; m >>= 1) s += __shfl_xor_sync(0xffffffffu, s, m);
    __shared__ float red[4];
    if ((threadIdx.x & 31) == 0) red[threadIdx.x >> 5] = s;
    __syncthreads();
    if (threadIdx.x == 0) g_cnorm[rc] = red[0] + red[1] + red[2] + red[3];
}

// ---------------- kernel 5: assign hi-only + gap flagging ----------------
__device__ __forceinline__ bool better(float v, int i, float bv, int bi) {
    return (v < bv) || (v == bv && i < bi);
}

struct Best2 { float bv; int bi; float sv; int si; };

__device__ __forceinline__ void upd(Best2& a, float v, int i) {
    if (better(v, i, a.bv, a.bi)) { a.sv = a.bv; a.si = a.bi; a.bv = v; a.bi = i; }
    else if (better(v, i, a.sv, a.si)) { a.sv = v; a.si = i; }
}

__device__ __forceinline__ void mrg(Best2& a, const Best2& o) {
    if (better(o.bv, o.bi, a.bv, a.bi)) {
        if (better(a.bv, a.bi, o.sv, o.si)) { a.sv = a.bv; a.si = a.bi; }
        else { a.sv = o.sv; a.si = o.si; }
        a.bv = o.bv; a.bi = o.bi;
    } else if (better(o.bv, o.bi, a.sv, a.si)) { a.sv = o.bv; a.si = o.bi; }
}

__global__ void __launch_bounds__(256) assign_hi_kernel()
{
    extern __shared__ char smem[];
    __shared__ float cns[kNC];
    __shared__ float cnmax_s;
    __shared__ Best2 sb[2][128];

    const int tid = threadIdx.x;
    const int lane = tid & 31, wid = tid >> 5;
    const int wm = wid & 3, wn = wid >> 2;
    const int gm = lane >> 2, gk = lane & 3;
    const int m0 = blockIdx.x * 128;
    const int r  = blockIdx.y;
    const uint32_t sbase = (uint32_t)__cvta_generic_to_shared(smem);
    const size_t cbase = (size_t)r * kNC * kD;

    if (tid < kNC) cns[tid] = g_cnorm[r * kNC + tid];

    float acc[2][4][4];
#pragma unroll
    for (int mt = 0; mt < 2; mt++)
#pragma unroll
        for (int nt = 0; nt < 4; nt++)
#pragma unroll
            for (int q = 0; q < 4; q++) acc[mt][nt][q] = 0.f;

    auto copy_chunk = [&](int c, int buf) {
        const int koff = c * 32;
        const uint32_t tb = sbase + (uint32_t)buf * kAsgBufB;
#pragma unroll
        for (int q = 0; q < 4; q++) {
            const int idx = q * 256 + tid;
            const int row = idx >> 3, f4 = idx & 7;
            const uint32_t doff = (uint32_t)(row * kPitch + f4 * 4) * 4;
            CP_ASYNC16(tb + doff, g_Bhi + (size_t)(m0 + row) * kD + koff + f4 * 4);
        }
#pragma unroll
        for (int q = 0; q < 2; q++) {
            const int idx = q * 256 + tid;
            const int row = idx >> 3, f4 = idx & 7;
            const uint32_t doff = (uint32_t)(row * kPitch + f4 * 4) * 4;
            CP_ASYNC16(tb + kATileB + doff, g_Chi + cbase + (size_t)row * kD + koff + f4 * 4);
        }
        CP_COMMIT();
    };

    copy_chunk(0, 0);
    copy_chunk(1, 1);

    for (int c = 0; c < kChunks; c++) {
        if (c < kChunks - 1) { CP_WAIT1(); } else { CP_WAIT0(); }
        __syncthreads();
        const int buf = c & 1;
        const float* Ah = reinterpret_cast<const float*>(smem + (size_t)buf * kAsgBufB);
        const float* Bh = reinterpret_cast<const float*>(smem + (size_t)buf * kAsgBufB + kATileB);

#pragma unroll
        for (int kk = 0; kk < 4; kk++) {
            const int kb = kk * 8 + gk;
            uint32_t ah[2][4];
#pragma unroll
            for (int mt = 0; mt < 2; mt++) {
                const int r0 = wm * 32 + mt * 16 + gm;
                ah[mt][0] = __float_as_uint(Ah[r0 * kPitch + kb]);
                ah[mt][1] = __float_as_uint(Ah[(r0 + 8) * kPitch + kb]);
                ah[mt][2] = __float_as_uint(Ah[r0 * kPitch + kb + 4]);
                ah[mt][3] = __float_as_uint(Ah[(r0 + 8) * kPitch + kb + 4]);
            }
#pragma unroll
            for (int nt = 0; nt < 4; nt++) {
                const int rB = wn * 32 + nt * 8 + gm;
                uint32_t bh0 = __float_as_uint(Bh[rB * kPitch + kb]);
                uint32_t bh1 = __float_as_uint(Bh[rB * kPitch + kb + 4]);
                MMA_TF32(acc[0][nt], ah[0], bh0, bh1);
                MMA_TF32(acc[1][nt], ah[1], bh0, bh1);
            }
        }
        __syncthreads();
        if (c + 2 < kChunks) copy_chunk(c + 2, (c + 2) & 1);
    }

    // best/2nd-best per point (lane covers rows mt*16 + {gm, gm+8}; cols via nt,gk)
#pragma unroll
    for (int mt = 0; mt < 2; mt++) {
#pragma unroll
        for (int half = 0; half < 2; half++) {
            Best2 b{3.402823466e38f, 0x7fffffff, 3.402823466e38f, 0x7fffffff};
#pragma unroll
            for (int nt = 0; nt < 4; nt++) {
                const int c0 = wn * 32 + nt * 8 + 2 * gk;
                upd(b, cns[c0]     - 2.f * acc[mt][nt][half * 2 + 0], c0);
                upd(b, cns[c0 + 1] - 2.f * acc[mt][nt][half * 2 + 1], c0 + 1);
            }
#pragma unroll
            for (int m = 1; m < 4; m <<= 1) {
                Best2 o;
                o.bv = __shfl_xor_sync(0xffffffffu, b.bv, m);
                o.bi = __shfl_xor_sync(0xffffffffu, b.bi, m);
                o.sv = __shfl_xor_sync(0xffffffffu, b.sv, m);
                o.si = __shfl_xor_sync(0xffffffffu, b.si, m);
                mrg(b, o);
            }
            if (gk == 0) sb[wn][wm * 32 + mt * 16 + half * 8 + gm] = b;
        }
    }
    __syncthreads();
    if (tid == 0) {
        float m = cns[0];
        for (int i = 1; i < kNC; i++) m = fmaxf(m, cns[i]);
        cnmax_s = m;
    }
    __syncthreads();
    if (tid < 128) {
        Best2 b = sb[0][tid];
        mrg(b, sb[1][tid]);
        float thresh = 0.012f * (sqrtf(fmaxf(cns[b.bi], 0.f)) + sqrtf(fmaxf(cnmax_s, 0.f)));
        g_labels[r * kN + m0 + tid] = b.bi;
        g_flags[r * kN + m0 + tid] = ((b.sv - b.bv) < thresh) ? 1 : 0;
    }
}

// ---------------- kernel 5b: exact fp32 fixup for flagged points -------------
__global__ void __launch_bounds__(256) fixup_kernel(const float* __restrict__ X)
{
    const int r = blockIdx.y;
    const int wid = threadIdx.x >> 5, lane = threadIdx.x & 31;
    const int p = blockIdx.x * 8 + wid;
    if (!g_flags[r * kN + p]) return;

    float x[16];
#pragma unroll
    for (int u = 0; u < 16; u++) x[u] = X[(size_t)p * kD + u * 32 + lane];

    const float* C = g_cent + (size_t)r * kNC * kD;
    float bv = 3.402823466e38f; int bi = 0x7fffffff;
    for (int c = 0; c < kNC; c++) {
        float s = 0.f;
#pragma unroll
        for (int u = 0; u < 16; u++) s = fmaf(x[u], C[(size_t)c * kD + u * 32 + lane], s);
#pragma unroll
        for (int m = 16; m >= 1; m >>= 1) s += __shfl_xor_sync(0xffffffffu, s, m);
        float v = g_cnorm[r * kNC + c] - 2.f * s;
        if (v < bv) { bv = v; bi = c; }   // strict <: lowest index on tie
    }
    if (lane == 0) g_labels[r * kN + p] = bi;
}

// ---------------- kernel 6a: point-centric partial sums (d-split) ------------
__global__ void __launch_bounds__(256) partial_kernel(const float* __restrict__ X)
{
    extern __shared__ float sm[];
    float* ssum = sm;                            // [kNC][256]
    int*   slab = (int*)(sm + kNC * 256);        // [kCHP]
    int*   scnt = (int*)(sm + kNC * 256) + kCHP; // [kNC]

    const int ch = blockIdx.x;
    const int r  = blockIdx.y >> 1, dh = blockIdx.y & 1;
    const int t = threadIdx.x;
    const int d = dh * 256 + t;
    const int p0 = ch * kCHP;
    const int* lab = g_labels + r * kN;

#pragma unroll
    for (int c = 0; c < kNC; c++) ssum[c * 256 + t] = 0.f;
    if (t < kNC) scnt[t] = 0;
    slab[t] = lab[p0 + t];
    __syncthreads();
    if (dh == 0) atomicAdd(&scnt[slab[t]], 1);
    __syncthreads();

    for (int i = 0; i < kCHP; i += 8) {
        float x0 = X[(size_t)(p0 + i + 0) * kD + d];
        float x1 = X[(size_t)(p0 + i + 1) * kD + d];
        float x2 = X[(size_t)(p0 + i + 2) * kD + d];
        float x3 = X[(size_t)(p0 + i + 3) * kD + d];
        float x4 = X[(size_t)(p0 + i + 4) * kD + d];
        float x5 = X[(size_t)(p0 + i + 5) * kD + d];
        float x6 = X[(size_t)(p0 + i + 6) * kD + d];
        float x7 = X[(size_t)(p0 + i + 7) * kD + d];
        int c0 = slab[i + 0], c1 = slab[i + 1], c2 = slab[i + 2], c3 = slab[i + 3];
        int c4 = slab[i + 4], c5 = slab[i + 5], c6 = slab[i + 6], c7 = slab[i + 7];
        ssum[c0 * 256 + t] += x0;
        ssum[c1 * 256 + t] += x1;
        ssum[c2 * 256 + t] += x2;
        ssum[c3 * 256 + t] += x3;
        ssum[c4 * 256 + t] += x4;
        ssum[c5 * 256 + t] += x5;
        ssum[c6 * 256 + t] += x6;
        ssum[c7 * 256 + t] += x7;
    }
    __syncthreads();

    const size_t base = (size_t)(r * kCH + ch) * kNC;
#pragma unroll
    for (int c = 0; c < kNC; c++)
        g_part[(base + c) * kD + d] = ssum[c * 256 + t];
    if (dh == 0 && t < kNC) g_pcnt[base + t] = scnt[t];
}

// ---------------- kernel 6b: combine partials -> centroid + norm -------------
__global__ void __launch_bounds__(512) combine_kernel()
{
    __shared__ float fred[16];
    const int c = blockIdx.x, r = blockIdx.y;
    const int t = threadIdx.x;
    const unsigned lane = t & 31;

    int cnt = 0;
    float sum = 0.f;
#pragma unroll
    for (int ch = 0; ch < kCH; ch++) {
        size_t base = (size_t)(r * kCH + ch) * kNC + c;
        cnt += g_pcnt[base];
        sum += g_part[base * kD + t];
    }
    const int rc = r * kNC + c;
    float oldc = g_cent[(size_t)rc * kD + t];
    float newc = (cnt > 0) ? (sum / (float)cnt) : oldc;
    g_cent[(size_t)rc * kD + t] = newc;

    float sq = newc * newc;
#pragma unroll
    for (int m = 16; m >= 1; m >>= 1) sq += __shfl_xor_sync(0xffffffffu, sq, m);
    if (lane == 0) fred[t >> 5] = sq;
    __syncthreads();
    if (t == 0) {
        float s = 0.f;
        for (int w = 0; w < 16; w++) s += fred[w];
        g_cnorm[rc] = s;
    }
}

// ---------------- kernel 7: scatter final output ----------------
__global__ void __launch_bounds__(256) scatter_kernel(
    const float* __restrict__ adj, float* __restrict__ out)
{
    int e = blockIdx.x * blockDim.x + threadIdx.x;
    int i = e >> 4;
    int j = g_knn[e];
    float v = adj[(size_t)i * kN + j];
    bool m = false;
#pragma unroll
    for (int r = 0; r < kNR; r++)
        m |= (g_labels[r * kN + i] == g_labels[r * kN + j]);
    out[(size_t)i * kN + j] = v + (m ? 1.f : 0.f);
}

// ---------------- launcher ----------------
extern "C" void kernel_launch(void* const* d_in, const int* in_sizes, int n_in,
                              void* d_out, int out_size)
{
    (void)in_sizes; (void)n_in; (void)out_size;
    const float* adj     = (const float*)d_in[0];
    const float* student = (const float*)d_in[1];
    const float* teacher = (const float*)d_in[2];
    float* out = (float*)d_out;

    constexpr size_t kPartSmem = (size_t)kNC * 256 * 4 + kCHP * 4 + kNC * 4;
    constexpr size_t kGemmSmem = 2 * (size_t)kGemmBufB;   // 73.7 KB
    constexpr size_t kAsgSmem  = 2 * (size_t)kAsgBufB;    // 55.3 KB
    constexpr size_t kTopSmem  = 256 * kCand * 8;         // 64 KB
    static cudaStream_t s2 = nullptr, s1 = nullptr;
    static cudaEvent_t ev_fork = nullptr, ev_join = nullptr, ev_main = nullptr, ev_split = nullptr;
    if (!s2) {
        int lo, hi;
        cudaDeviceGetStreamPriorityRange(&lo, &hi);
        cudaStreamCreateWithPriority(&s2, cudaStreamNonBlocking, hi);
        cudaStreamCreateWithPriority(&s1, cudaStreamNonBlocking, lo);
        cudaEventCreateWithFlags(&ev_fork, cudaEventDisableTiming);
        cudaEventCreateWithFlags(&ev_join, cudaEventDisableTiming);
        cudaEventCreateWithFlags(&ev_main, cudaEventDisableTiming);
        cudaEventCreateWithFlags(&ev_split, cudaEventDisableTiming);
        cudaFuncSetAttribute(partial_kernel,
                             cudaFuncAttributeMaxDynamicSharedMemorySize, (int)kPartSmem);
        cudaFuncSetAttribute(gemm_hi_kernel,
                             cudaFuncAttributeMaxDynamicSharedMemorySize, (int)kGemmSmem);
        cudaFuncSetAttribute(assign_hi_kernel,
                             cudaFuncAttributeMaxDynamicSharedMemorySize, (int)kAsgSmem);
        cudaFuncSetAttribute(topk32_kernel,
                             cudaFuncAttributeMaxDynamicSharedMemorySize, (int)kTopSmem);
    }

    IdxArr ia;
    compute_init_indices(ia.v);

    cudaEventRecord(ev_fork, 0);
    cudaStreamWaitEvent(s2, ev_fork, 0);
    cudaStreamWaitEvent(s1, ev_fork, 0);

    // s1: tf32 hi split (also feeds assign's teacher tiles)
    split_hi_kernel<<<(kN * kD) / (256 * 4), 256, 0, s1>>>(student, teacher);
    cudaEventRecord(ev_split, s1);

    // s2: serial kmeans chain (hi-only tensor assign + exact fixup)
    gather_kernel<<<kRC, 128, 0, s2>>>(teacher, ia);
    cnorm_kernel<<<kRC, 128, 0, s2>>>();
    split_cent_hi_kernel<<<(kRC * kD) / (256 * 4), 256, 0, s2>>>();
    cudaStreamWaitEvent(s2, ev_split, 0);
    dim3 ga(kN / 128, kNR), gf(kN / 8, kNR), gp(kCH, kNR * 2), gc(kNC, kNR);
    for (int it = 0; it < kIters; it++) {
        assign_hi_kernel<<<ga, 256, kAsgSmem, s2>>>();
        fixup_kernel<<<gf, 256, 0, s2>>>(teacher);
        partial_kernel<<<gp, 256, kPartSmem, s2>>>(teacher);
        combine_kernel<<<gc, 512, 0, s2>>>();
        split_cent_hi_kernel<<<(kRC * kD) / (256 * 4), 256, 0, s2>>>();
    }
    assign_hi_kernel<<<ga, 256, kAsgSmem, s2>>>();
    fixup_kernel<<<gf, 256, 0, s2>>>(teacher);
    cudaEventRecord(ev_join, s2);

    // s1: hi-only sim GEMM -> top-32 candidates -> fp32 rescore -> zero out
    dim3 g1(kN / 128, kN / 128);
    gemm_hi_kernel<<<g1, 256, kGemmSmem, s1>>>(out);
    topk32_kernel<<<kN, 256, kTopSmem, s1>>>(out);
    rescore_kernel<<<kN, 256, 0, s1>>>(student, teacher);
    cudaMemsetAsync(d_out, 0, (size_t)kN * kN * sizeof(float), s1);
    cudaEventRecord(ev_main, s1);

    cudaStreamWaitEvent(0, ev_join, 0);
    cudaStreamWaitEvent(0, ev_main, 0);
    scatter_kernel<<<kN * kTK / 256, 256>>>(adj, out);
}

// round 13
// speedup vs baseline: 1.0454x; 1.0454x over previous
#include <cuda_runtime.h>
#include <cstdint>
#include <cstring>
#include <vector>
#include <algorithm>

namespace {
constexpr int kN = 8192, kD = 512, kNC = 64, kNR = 5, kRC = kNC * kNR;
constexpr int kTK = 16, kIters = 20;
constexpr int kCH = 32, kCHP = kN / kCH;   // 32 chunks x 256 points
constexpr int kCand = 32;                  // topk candidate count

// ---------------- host-side JAX threefry2x32 ----------------
struct U2 { uint32_t a, b; };
static inline uint32_t rotl32(uint32_t v, int r) { return (v << r) | (v >> (32 - r)); }

static U2 threefry(U2 key, uint32_t x0, uint32_t x1) {
    uint32_t ks0 = key.a, ks1 = key.b, ks2 = key.a ^ key.b ^ 0x1BD11BDAu;
    const int ra[4] = {13, 15, 26, 6}, rb[4] = {17, 29, 16, 24};
    x0 += ks0; x1 += ks1;
    for (int i = 0; i < 4; i++) { x0 += x1; x1 = rotl32(x1, ra[i]); x1 ^= x0; }
    x0 += ks1; x1 += ks2 + 1u;
    for (int i = 0; i < 4; i++) { x0 += x1; x1 = rotl32(x1, rb[i]); x1 ^= x0; }
    x0 += ks2; x1 += ks0 + 2u;
    for (int i = 0; i < 4; i++) { x0 += x1; x1 = rotl32(x1, ra[i]); x1 ^= x0; }
    x0 += ks0; x1 += ks1 + 3u;
    for (int i = 0; i < 4; i++) { x0 += x1; x1 = rotl32(x1, rb[i]); x1 ^= x0; }
    x0 += ks1; x1 += ks2 + 4u;
    for (int i = 0; i < 4; i++) { x0 += x1; x1 = rotl32(x1, ra[i]); x1 ^= x0; }
    x0 += ks2; x1 += ks0 + 5u;
    return {x0, x1};
}

constexpr bool kPartitionable = true;

static void split_keys(U2 key, int n, U2* out) {
    if (kPartitionable) {
        for (int i = 0; i < n; i++) out[i] = threefry(key, 0u, (uint32_t)i);
    } else {
        std::vector<uint32_t> o(2 * n);
        for (int i = 0; i < n; i++) {
            U2 y = threefry(key, (uint32_t)i, (uint32_t)(n + i));
            o[i] = y.a; o[n + i] = y.b;
        }
        for (int j = 0; j < n; j++) out[j] = { o[2 * j], o[2 * j + 1] };
    }
}

static void random_bits32(U2 key, int n, uint32_t* bits) {
    if (kPartitionable) {
        for (int i = 0; i < n; i++) {
            U2 y = threefry(key, 0u, (uint32_t)i);
            bits[i] = y.a ^ y.b;
        }
    } else {
        int h = n / 2;
        for (int i = 0; i < h; i++) {
            U2 y = threefry(key, (uint32_t)i, (uint32_t)(h + i));
            bits[i] = y.a; bits[h + i] = y.b;
        }
    }
}

static void compute_init_indices(int out_idx[kRC]) {
    U2 master{0u, 1234u};
    U2 runkeys[kNR];
    split_keys(master, kNR, runkeys);
    std::vector<int> val(kN), tmp(kN);
    std::vector<uint64_t> kv(kN);
    std::vector<uint32_t> bits(kN);
    for (int r = 0; r < kNR; r++) {
        for (int i = 0; i < kN; i++) val[i] = i;
        U2 cur = runkeys[r];
        for (int round = 0; round < 2; round++) {
            U2 nk[2];
            split_keys(cur, 2, nk);
            cur = nk[0];
            random_bits32(nk[1], kN, bits.data());
            for (int i = 0; i < kN; i++)
                kv[i] = ((uint64_t)bits[i] << 32) | (uint32_t)i;
            std::sort(kv.begin(), kv.end());
            for (int i = 0; i < kN; i++) tmp[i] = val[(uint32_t)(kv[i] & 0xffffffffu)];
            val.swap(tmp);
        }
        for (int c = 0; c < kNC; c++) out_idx[r * kNC + c] = val[c];
    }
}
} // namespace

// ---------------- device scratch ----------------
__device__ float g_cent[kRC * kD];
__device__ float g_cnorm[kRC];
__device__ int   g_labels[kNR * kN];
__device__ int4  g_cand4[kNR * kN];
__device__ int   g_knn[kN * kTK];
__device__ int   g_cand[kN * kCand];
__device__ float g_part[(size_t)kNR * kCH * kNC * kD];
__device__ int   g_pcnt[kNR * kCH * kNC];
__device__ float g_Ahi[(size_t)kN * kD];   // student hi (tf32)
__device__ float g_Bhi[(size_t)kN * kD];   // teacher hi (tf32)
__device__ float g_Chi[(size_t)kRC * kD];  // centroid hi (tf32)

struct IdxArr { int v[kRC]; };

// ---------------- tf32 helpers ----------------
__device__ __forceinline__ float tf32r(float x) {
    uint32_t u; asm("cvt.rna.tf32.f32 %0,%1;" : "=r"(u) : "f"(x));
    return __uint_as_float(u);
}

#define MMA_TF32(d, a, b0, b1) \
    asm volatile( \
        "mma.sync.aligned.m16n8k8.row.col.f32.tf32.tf32.f32 " \
        "{%0,%1,%2,%3}, {%4,%5,%6,%7}, {%8,%9}, {%0,%1,%2,%3};" \
        : "+f"((d)[0]), "+f"((d)[1]), "+f"((d)[2]), "+f"((d)[3]) \
        : "r"((a)[0]), "r"((a)[1]), "r"((a)[2]), "r"((a)[3]), \
          "r"(b0), "r"(b1))

#define CP_ASYNC16(dst, src) \
    asm volatile("cp.async.cg.shared.global [%0], [%1], 16;" :: "r"(dst), "l"(src) : "memory")
#define CP_COMMIT() asm volatile("cp.async.commit_group;" ::: "memory")
#define CP_WAIT1()  asm volatile("cp.async.wait_group 1;" ::: "memory")
#define CP_WAIT0()  asm volatile("cp.async.wait_group 0;" ::: "memory")

namespace {
constexpr int kPitch = 36;
constexpr int kATileB = 128 * kPitch * 4;   // 18432
constexpr int kBTileB = 64 * kPitch * 4;    // 9216
constexpr int kChunks = kD / 32;            // 16
constexpr int kGemmBufB = 2 * kATileB;              // Ahi + Bhi (both 128 rows)
constexpr int kAsgBufB  = kATileB + kBTileB;        // teacher(128) + Chi(64)
}

// ---------------- kernel 0: fp32 -> tf32 hi (inputs) ----------------
__global__ void __launch_bounds__(256) split_hi_kernel(const float* __restrict__ A,
                                                       const float* __restrict__ B)
{
    size_t i = ((size_t)blockIdx.x * 256 + threadIdx.x) * 4;
    float4 a = *reinterpret_cast<const float4*>(A + i);
    float4 b = *reinterpret_cast<const float4*>(B + i);
    float4 ah, bh;
    ah.x = tf32r(a.x); ah.y = tf32r(a.y); ah.z = tf32r(a.z); ah.w = tf32r(a.w);
    bh.x = tf32r(b.x); bh.y = tf32r(b.y); bh.z = tf32r(b.z); bh.w = tf32r(b.w);
    *reinterpret_cast<float4*>(g_Ahi + i) = ah;
    *reinterpret_cast<float4*>(g_Bhi + i) = bh;
}

__global__ void __launch_bounds__(256) split_cent_hi_kernel()
{
    size_t i = ((size_t)blockIdx.x * 256 + threadIdx.x) * 4;
    float4 c = *reinterpret_cast<const float4*>(g_cent + i);
    float4 ch;
    ch.x = tf32r(c.x); ch.y = tf32r(c.y); ch.z = tf32r(c.z); ch.w = tf32r(c.w);
    *reinterpret_cast<float4*>(g_Chi + i) = ch;
}

// ---------------- kernel 1: sim GEMM, hi-only tf32 ----------------
__global__ void __launch_bounds__(256) gemm_hi_kernel(float* __restrict__ C)
{
    extern __shared__ char smem[];
    const int tid = threadIdx.x;
    const int lane = tid & 31, wid = tid >> 5;
    const int wm = wid & 3, wn = wid >> 2;
    const int gm = lane >> 2, gk = lane & 3;
    const int n0 = blockIdx.x * 128, m0 = blockIdx.y * 128;
    const uint32_t sbase = (uint32_t)__cvta_generic_to_shared(smem);

    float acc[2][8][4];
#pragma unroll
    for (int mt = 0; mt < 2; mt++)
#pragma unroll
        for (int nt = 0; nt < 8; nt++)
#pragma unroll
            for (int q = 0; q < 4; q++) acc[mt][nt][q] = 0.f;

    auto copy_chunk = [&](int c, int buf) {
        const int koff = c * 32;
        const uint32_t tb = sbase + (uint32_t)buf * kGemmBufB;
#pragma unroll
        for (int q = 0; q < 4; q++) {
            const int idx = q * 256 + tid;
            const int row = idx >> 3, f4 = idx & 7;
            const uint32_t doff = (uint32_t)(row * kPitch + f4 * 4) * 4;
            CP_ASYNC16(tb + doff, g_Ahi + (size_t)(m0 + row) * kD + koff + f4 * 4);
            CP_ASYNC16(tb + kATileB + doff, g_Bhi + (size_t)(n0 + row) * kD + koff + f4 * 4);
        }
        CP_COMMIT();
    };

    copy_chunk(0, 0);
    copy_chunk(1, 1);

    for (int c = 0; c < kChunks; c++) {
        if (c < kChunks - 1) { CP_WAIT1(); } else { CP_WAIT0(); }
        __syncthreads();
        const int buf = c & 1;
        const float* Ah = reinterpret_cast<const float*>(smem + (size_t)buf * kGemmBufB);
        const float* Bh = reinterpret_cast<const float*>(smem + (size_t)buf * kGemmBufB + kATileB);

#pragma unroll
        for (int kk = 0; kk < 4; kk++) {
            const int kb = kk * 8 + gk;
            uint32_t ah[2][4];
#pragma unroll
            for (int mt = 0; mt < 2; mt++) {
                const int r0 = wm * 32 + mt * 16 + gm;
                ah[mt][0] = __float_as_uint(Ah[r0 * kPitch + kb]);
                ah[mt][1] = __float_as_uint(Ah[(r0 + 8) * kPitch + kb]);
                ah[mt][2] = __float_as_uint(Ah[r0 * kPitch + kb + 4]);
                ah[mt][3] = __float_as_uint(Ah[(r0 + 8) * kPitch + kb + 4]);
            }
#pragma unroll
            for (int nt = 0; nt < 8; nt++) {
                const int rB = wn * 64 + nt * 8 + gm;
                uint32_t bh0 = __float_as_uint(Bh[rB * kPitch + kb]);
                uint32_t bh1 = __float_as_uint(Bh[rB * kPitch + kb + 4]);
                MMA_TF32(acc[0][nt], ah[0], bh0, bh1);
                MMA_TF32(acc[1][nt], ah[1], bh0, bh1);
            }
        }
        __syncthreads();
        if (c + 2 < kChunks) copy_chunk(c + 2, (c + 2) & 1);
    }

#pragma unroll
    for (int mt = 0; mt < 2; mt++) {
#pragma unroll
        for (int nt = 0; nt < 8; nt++) {
            const int r0 = m0 + wm * 32 + mt * 16 + gm;
            const int r1 = r0 + 8;
            const int col = n0 + wn * 64 + nt * 8 + 2 * gk;
            float2 v0, v1;
            v0.x = acc[mt][nt][0] + ((r0 == col) ? 10.f : 0.f);
            v0.y = acc[mt][nt][1] + ((r0 == col + 1) ? 10.f : 0.f);
            v1.x = acc[mt][nt][2] + ((r1 == col) ? 10.f : 0.f);
            v1.y = acc[mt][nt][3] + ((r1 == col + 1) ? 10.f : 0.f);
            *reinterpret_cast<float2*>(&C[(size_t)r0 * kN + col]) = v0;
            *reinterpret_cast<float2*>(&C[(size_t)r1 * kN + col]) = v1;
        }
    }
}

// ---------------- kernel 2: per-row top-32 candidates (tf32 values) ----------
__device__ __forceinline__ bool beats(float v1, int i1, float v2, int i2) {
    return (v1 > v2) || (v1 == v2 && i1 < i2);
}

__global__ void __launch_bounds__(256) topk32_kernel(const float* __restrict__ sim)
{
    extern __shared__ char smem[];
    float* sv = reinterpret_cast<float*>(smem);                 // [256][32]
    int*   si = reinterpret_cast<int*>(sv + 256 * kCand);       // [256][32]
    const int row = blockIdx.x, t = threadIdx.x;
    float tv[kCand]; int ti[kCand];
#pragma unroll
    for (int k = 0; k < kCand; k++) { tv[k] = -3.402823466e38f; ti[k] = 0x7fffffff; }

    const float* rp = sim + (size_t)row * kN;
    for (int j = t; j < kN; j += 256) {
        float v = rp[j];
        if (beats(v, j, tv[kCand - 1], ti[kCand - 1])) {
            float cv = v; int ci = j;
#pragma unroll
            for (int k = 0; k < kCand; k++) {
                if (beats(cv, ci, tv[k], ti[k])) {
                    float fv = tv[k]; int fi = ti[k];
                    tv[k] = cv; ti[k] = ci; cv = fv; ci = fi;
                }
            }
        }
    }
#pragma unroll
    for (int k = 0; k < kCand; k++) { sv[t * kCand + k] = tv[k]; si[t * kCand + k] = ti[k]; }
    __syncthreads();

    for (int s = 128; s >= 1; s >>= 1) {
        if (t < s) {
            float mv[kCand]; int mi[kCand];
            int ia = 0, ib = 0;
#pragma unroll
            for (int k = 0; k < kCand; k++) {
                float av = sv[t * kCand + ia], bw = sv[(t + s) * kCand + ib];
                int   ai = si[t * kCand + ia], bj = si[(t + s) * kCand + ib];
                bool ta = beats(av, ai, bw, bj);
                mv[k] = ta ? av : bw; mi[k] = ta ? ai : bj;
                if (ta) ia++; else ib++;
            }
#pragma unroll
            for (int k = 0; k < kCand; k++) { sv[t * kCand + k] = mv[k]; si[t * kCand + k] = mi[k]; }
        }
        __syncthreads();
    }
    if (t < kCand) g_cand[row * kCand + t] = si[t];
}

// ---------------- kernel 2b: fp32 rescore of candidates -> exact top-16 ------
__global__ void __launch_bounds__(256) rescore_kernel(const float* __restrict__ S,
                                                      const float* __restrict__ T)
{
    __shared__ float cv[kCand];
    __shared__ int   ci[kCand];
    const int row = blockIdx.x;
    const int tid = threadIdx.x;
    const int wid = tid >> 5, lane = tid & 31;

#pragma unroll
    for (int k = 0; k < 4; k++) {
        const int slot = wid + 8 * k;
        const int cand = g_cand[row * kCand + slot];
        float s = 0.f;
#pragma unroll
        for (int u = 0; u < 16; u++)
            s = fmaf(S[(size_t)row * kD + u * 32 + lane],
                     T[(size_t)cand * kD + u * 32 + lane], s);
#pragma unroll
        for (int m = 16; m >= 1; m >>= 1) s += __shfl_xor_sync(0xffffffffu, s, m);
        if (lane == 0) {
            if (cand == row) s += 10.f;
            cv[slot] = s; ci[slot] = cand;
        }
    }
    __syncthreads();
    if (tid == 0) {
        unsigned used = 0;
        for (int k = 0; k < kTK; k++) {
            float bv = -3.402823466e38f; int bi = 0x7fffffff, bs = -1;
            for (int q = 0; q < kCand; q++) {
                if (used & (1u << q)) continue;
                if (beats(cv[q], ci[q], bv, bi)) { bv = cv[q]; bi = ci[q]; bs = q; }
            }
            used |= (1u << bs);
            g_knn[row * kTK + k] = bi;
        }
    }
}

// ---------------- kernel 3/4: gather + norms ----------------
__global__ void gather_kernel(const float* __restrict__ X, IdxArr ia)
{
    int b = blockIdx.x;
    int src = ia.v[b];
    for (int d = threadIdx.x; d < kD; d += blockDim.x)
        g_cent[(size_t)b * kD + d] = X[(size_t)src * kD + d];
}

__global__ void __launch_bounds__(128) cnorm_kernel()
{
    int rc = blockIdx.x;
    float s = 0.f;
    for (int d = threadIdx.x; d < kD; d += 128) {
        float v = g_cent[(size_t)rc * kD + d];
        s = fmaf(v, v, s);
    }
#pragma unroll
    for (int m = 16; m >= 1; m >>= 1) s += __shfl_xor_sync(0xffffffffu, s, m);
    __shared__ float red[4];
    if ((threadIdx.x & 31) == 0) red[threadIdx.x >> 5] = s;
    __syncthreads();
    if (threadIdx.x == 0) g_cnorm[rc] = red[0] + red[1] + red[2] + red[3];
}

// ---------------- kernel 5: assign hi-only -> top-4 candidates ----------------
__device__ __forceinline__ bool better(float v, int i, float bv, int bi) {
    return (v < bv) || (v == bv && i < bi);
}

__global__ void __launch_bounds__(256) assign_hi_kernel()
{
    extern __shared__ char smem[];
    __shared__ float cns[kNC];
    __shared__ float sd4[2][128][4];
    __shared__ int   si4[2][128][4];

    const int tid = threadIdx.x;
    const int lane = tid & 31, wid = tid >> 5;
    const int wm = wid & 3, wn = wid >> 2;
    const int gm = lane >> 2, gk = lane & 3;
    const int m0 = blockIdx.x * 128;
    const int r  = blockIdx.y;
    const uint32_t sbase = (uint32_t)__cvta_generic_to_shared(smem);
    const size_t cbase = (size_t)r * kNC * kD;

    if (tid < kNC) cns[tid] = g_cnorm[r * kNC + tid];

    float acc[2][4][4];
#pragma unroll
    for (int mt = 0; mt < 2; mt++)
#pragma unroll
        for (int nt = 0; nt < 4; nt++)
#pragma unroll
            for (int q = 0; q < 4; q++) acc[mt][nt][q] = 0.f;

    auto copy_chunk = [&](int c, int buf) {
        const int koff = c * 32;
        const uint32_t tb = sbase + (uint32_t)buf * kAsgBufB;
#pragma unroll
        for (int q = 0; q < 4; q++) {
            const int idx = q * 256 + tid;
            const int row = idx >> 3, f4 = idx & 7;
            const uint32_t doff = (uint32_t)(row * kPitch + f4 * 4) * 4;
            CP_ASYNC16(tb + doff, g_Bhi + (size_t)(m0 + row) * kD + koff + f4 * 4);
        }
#pragma unroll
        for (int q = 0; q < 2; q++) {
            const int idx = q * 256 + tid;
            const int row = idx >> 3, f4 = idx & 7;
            const uint32_t doff = (uint32_t)(row * kPitch + f4 * 4) * 4;
            CP_ASYNC16(tb + kATileB + doff, g_Chi + cbase + (size_t)row * kD + koff + f4 * 4);
        }
        CP_COMMIT();
    };

    copy_chunk(0, 0);
    copy_chunk(1, 1);

    for (int c = 0; c < kChunks; c++) {
        if (c < kChunks - 1) { CP_WAIT1(); } else { CP_WAIT0(); }
        __syncthreads();
        const int buf = c & 1;
        const float* Ah = reinterpret_cast<const float*>(smem + (size_t)buf * kAsgBufB);
        const float* Bh = reinterpret_cast<const float*>(smem + (size_t)buf * kAsgBufB + kATileB);

#pragma unroll
        for (int kk = 0; kk < 4; kk++) {
            const int kb = kk * 8 + gk;
            uint32_t ah[2][4];
#pragma unroll
            for (int mt = 0; mt < 2; mt++) {
                const int r0 = wm * 32 + mt * 16 + gm;
                ah[mt][0] = __float_as_uint(Ah[r0 * kPitch + kb]);
                ah[mt][1] = __float_as_uint(Ah[(r0 + 8) * kPitch + kb]);
                ah[mt][2] = __float_as_uint(Ah[r0 * kPitch + kb + 4]);
                ah[mt][3] = __float_as_uint(Ah[(r0 + 8) * kPitch + kb + 4]);
            }
#pragma unroll
            for (int nt = 0; nt < 4; nt++) {
                const int rB = wn * 32 + nt * 8 + gm;
                uint32_t bh0 = __float_as_uint(Bh[rB * kPitch + kb]);
                uint32_t bh1 = __float_as_uint(Bh[rB * kPitch + kb + 4]);
                MMA_TF32(acc[0][nt], ah[0], bh0, bh1);
                MMA_TF32(acc[1][nt], ah[1], bh0, bh1);
            }
        }
        __syncthreads();
        if (c + 2 < kChunks) copy_chunk(c + 2, (c + 2) & 1);
    }

    // top-4 candidates per point: sorted insert per lane, shfl merge over quad,
    // cross-warp (wn) merge in smem.
#pragma unroll
    for (int mt = 0; mt < 2; mt++) {
#pragma unroll
        for (int half = 0; half < 2; half++) {
            float tv[4]; int ti[4];
#pragma unroll
            for (int q = 0; q < 4; q++) { tv[q] = 3.402823466e38f; ti[q] = 0x7fffffff; }
#pragma unroll
            for (int nt = 0; nt < 4; nt++) {
                const int c0 = wn * 32 + nt * 8 + 2 * gk;
#pragma unroll
                for (int hh = 0; hh < 2; hh++) {
                    float v = cns[c0 + hh] - 2.f * acc[mt][nt][half * 2 + hh];
                    int   i = c0 + hh;
                    if (better(v, i, tv[3], ti[3])) {
                        float cvv = v; int cii = i;
#pragma unroll
                        for (int q = 0; q < 4; q++) {
                            if (better(cvv, cii, tv[q], ti[q])) {
                                float fv = tv[q]; int fi = ti[q];
                                tv[q] = cvv; ti[q] = cii; cvv = fv; cii = fi;
                            }
                        }
                    }
                }
            }
#pragma unroll
            for (int m = 1; m < 4; m <<= 1) {   // merge sorted-4 lists over quad
                float ov[4]; int oi[4];
#pragma unroll
                for (int q = 0; q < 4; q++) {
                    ov[q] = __shfl_xor_sync(0xffffffffu, tv[q], m);
                    oi[q] = __shfl_xor_sync(0xffffffffu, ti[q], m);
                }
                float mv[4]; int mi[4];
                int ia = 0, ib = 0;
#pragma unroll
                for (int q = 0; q < 4; q++) {
                    bool ta = better(tv[ia], ti[ia], ov[ib], oi[ib]);
                    mv[q] = ta ? tv[ia] : ov[ib];
                    mi[q] = ta ? ti[ia] : oi[ib];
                    if (ta) ia++; else ib++;
                }
#pragma unroll
                for (int q = 0; q < 4; q++) { tv[q] = mv[q]; ti[q] = mi[q]; }
            }
            if (gk == 0) {
                const int rl = wm * 32 + mt * 16 + half * 8 + gm;
#pragma unroll
                for (int q = 0; q < 4; q++) { sd4[wn][rl][q] = tv[q]; si4[wn][rl][q] = ti[q]; }
            }
        }
    }
    __syncthreads();
    if (tid < 128) {
        float mv[4]; int mi[4];
        int ia = 0, ib = 0;
#pragma unroll
        for (int q = 0; q < 4; q++) {
            bool ta = better(sd4[0][tid][ia], si4[0][tid][ia], sd4[1][tid][ib], si4[1][tid][ib]);
            mv[q] = ta ? sd4[0][tid][ia] : sd4[1][tid][ib];
            mi[q] = ta ? si4[0][tid][ia] : si4[1][tid][ib];
            if (ta) ia++; else ib++;
        }
        (void)mv;
        g_cand4[r * kN + m0 + tid] = make_int4(mi[0], mi[1], mi[2], mi[3]);
    }
}

// ---------------- kernel 5b: exact fp32 refine over 4 candidates -------------
__global__ void __launch_bounds__(256) refine_kernel(const float* __restrict__ X)
{
    const int r = blockIdx.y;
    const int wid = threadIdx.x >> 5, lane = threadIdx.x & 31;
    const int p = blockIdx.x * 8 + wid;
    const int4 cd = g_cand4[r * kN + p];
    const int cands[4] = {cd.x, cd.y, cd.z, cd.w};

    float x[16];
#pragma unroll
    for (int u = 0; u < 16; u++) x[u] = X[(size_t)p * kD + u * 32 + lane];

    const float* C = g_cent + (size_t)r * kNC * kD;
    float bv = 3.402823466e38f; int bi = 0x7fffffff;
#pragma unroll
    for (int q = 0; q < 4; q++) {
        const int c = cands[q];
        float s = 0.f;
#pragma unroll
        for (int u = 0; u < 16; u++) s = fmaf(x[u], C[(size_t)c * kD + u * 32 + lane], s);
#pragma unroll
        for (int m = 16; m >= 1; m >>= 1) s += __shfl_xor_sync(0xffffffffu, s, m);
        float v = g_cnorm[r * kNC + c] - 2.f * s;
        if (better(v, c, bv, bi)) { bv = v; bi = c; }
    }
    if (lane == 0) g_labels[r * kN + p] = bi;
}

// ---------------- kernel 6a: point-centric partial sums (d-split) ------------
__global__ void __launch_bounds__(256) partial_kernel(const float* __restrict__ X)
{
    extern __shared__ float sm[];
    float* ssum = sm;                            // [kNC][256]
    int*   slab = (int*)(sm + kNC * 256);        // [kCHP]
    int*   scnt = (int*)(sm + kNC * 256) + kCHP; // [kNC]

    const int ch = blockIdx.x;
    const int r  = blockIdx.y >> 1, dh = blockIdx.y & 1;
    const int t = threadIdx.x;
    const int d = dh * 256 + t;
    const int p0 = ch * kCHP;
    const int* lab = g_labels + r * kN;

#pragma unroll
    for (int c = 0; c < kNC; c++) ssum[c * 256 + t] = 0.f;
    if (t < kNC) scnt[t] = 0;
    slab[t] = lab[p0 + t];
    __syncthreads();
    if (dh == 0) atomicAdd(&scnt[slab[t]], 1);
    __syncthreads();

    for (int i = 0; i < kCHP; i += 8) {
        float x0 = X[(size_t)(p0 + i + 0) * kD + d];
        float x1 = X[(size_t)(p0 + i + 1) * kD + d];
        float x2 = X[(size_t)(p0 + i + 2) * kD + d];
        float x3 = X[(size_t)(p0 + i + 3) * kD + d];
        float x4 = X[(size_t)(p0 + i + 4) * kD + d];
        float x5 = X[(size_t)(p0 + i + 5) * kD + d];
        float x6 = X[(size_t)(p0 + i + 6) * kD + d];
        float x7 = X[(size_t)(p0 + i + 7) * kD + d];
        int c0 = slab[i + 0], c1 = slab[i + 1], c2 = slab[i + 2], c3 = slab[i + 3];
        int c4 = slab[i + 4], c5 = slab[i + 5], c6 = slab[i + 6], c7 = slab[i + 7];
        ssum[c0 * 256 + t] += x0;
        ssum[c1 * 256 + t] += x1;
        ssum[c2 * 256 + t] += x2;
        ssum[c3 * 256 + t] += x3;
        ssum[c4 * 256 + t] += x4;
        ssum[c5 * 256 + t] += x5;
        ssum[c6 * 256 + t] += x6;
        ssum[c7 * 256 + t] += x7;
    }
    __syncthreads();

    const size_t base = (size_t)(r * kCH + ch) * kNC;
#pragma unroll
    for (int c = 0; c < kNC; c++)
        g_part[(base + c) * kD + d] = ssum[c * 256 + t];
    if (dh == 0 && t < kNC) g_pcnt[base + t] = scnt[t];
}

// ---------------- kernel 6b: combine partials -> centroid + norm -------------
__global__ void __launch_bounds__(512) combine_kernel()
{
    __shared__ float fred[16];
    const int c = blockIdx.x, r = blockIdx.y;
    const int t = threadIdx.x;
    const unsigned lane = t & 31;

    int cnt = 0;
    float sum = 0.f;
#pragma unroll
    for (int ch = 0; ch < kCH; ch++) {
        size_t base = (size_t)(r * kCH + ch) * kNC + c;
        cnt += g_pcnt[base];
        sum += g_part[base * kD + t];
    }
    const int rc = r * kNC + c;
    float oldc = g_cent[(size_t)rc * kD + t];
    float newc = (cnt > 0) ? (sum / (float)cnt) : oldc;
    g_cent[(size_t)rc * kD + t] = newc;

    float sq = newc * newc;
#pragma unroll
    for (int m = 16; m >= 1; m >>= 1) sq += __shfl_xor_sync(0xffffffffu, sq, m);
    if (lane == 0) fred[t >> 5] = sq;
    __syncthreads();
    if (t == 0) {
        float s = 0.f;
        for (int w = 0; w < 16; w++) s += fred[w];
        g_cnorm[rc] = s;
    }
}

// ---------------- kernel 7: scatter final output ----------------
__global__ void __launch_bounds__(256) scatter_kernel(
    const float* __restrict__ adj, float* __restrict__ out)
{
    int e = blockIdx.x * blockDim.x + threadIdx.x;
    int i = e >> 4;
    int j = g_knn[e];
    float v = adj[(size_t)i * kN + j];
    bool m = false;
#pragma unroll
    for (int r = 0; r < kNR; r++)
        m |= (g_labels[r * kN + i] == g_labels[r * kN + j]);
    out[(size_t)i * kN + j] = v + (m ? 1.f : 0.f);
}

// ---------------- launcher ----------------
extern "C" void kernel_launch(void* const* d_in, const int* in_sizes, int n_in,
                              void* d_out, int out_size)
{
    (void)in_sizes; (void)n_in; (void)out_size;
    const float* adj     = (const float*)d_in[0];
    const float* student = (const float*)d_in[1];
    const float* teacher = (const float*)d_in[2];
    float* out = (float*)d_out;

    constexpr size_t kPartSmem = (size_t)kNC * 256 * 4 + kCHP * 4 + kNC * 4;
    constexpr size_t kGemmSmem = 2 * (size_t)kGemmBufB;   // 73.7 KB
    constexpr size_t kAsgSmem  = 2 * (size_t)kAsgBufB;    // 55.3 KB
    constexpr size_t kTopSmem  = 256 * kCand * 8;         // 64 KB
    static cudaStream_t s2 = nullptr, s1 = nullptr;
    static cudaEvent_t ev_fork = nullptr, ev_join = nullptr, ev_main = nullptr, ev_split = nullptr;
    if (!s2) {
        int lo, hi;
        cudaDeviceGetStreamPriorityRange(&lo, &hi);
        cudaStreamCreateWithPriority(&s2, cudaStreamNonBlocking, hi);
        cudaStreamCreateWithPriority(&s1, cudaStreamNonBlocking, lo);
        cudaEventCreateWithFlags(&ev_fork, cudaEventDisableTiming);
        cudaEventCreateWithFlags(&ev_join, cudaEventDisableTiming);
        cudaEventCreateWithFlags(&ev_main, cudaEventDisableTiming);
        cudaEventCreateWithFlags(&ev_split, cudaEventDisableTiming);
        cudaFuncSetAttribute(partial_kernel,
                             cudaFuncAttributeMaxDynamicSharedMemorySize, (int)kPartSmem);
        cudaFuncSetAttribute(gemm_hi_kernel,
                             cudaFuncAttributeMaxDynamicSharedMemorySize, (int)kGemmSmem);
        cudaFuncSetAttribute(assign_hi_kernel,
                             cudaFuncAttributeMaxDynamicSharedMemorySize, (int)kAsgSmem);
        cudaFuncSetAttribute(topk32_kernel,
                             cudaFuncAttributeMaxDynamicSharedMemorySize, (int)kTopSmem);
    }

    IdxArr ia;
    compute_init_indices(ia.v);

    cudaEventRecord(ev_fork, 0);
    cudaStreamWaitEvent(s2, ev_fork, 0);
    cudaStreamWaitEvent(s1, ev_fork, 0);

    // s1: tf32 hi split (also feeds assign's teacher tiles)
    split_hi_kernel<<<(kN * kD) / (256 * 4), 256, 0, s1>>>(student, teacher);
    cudaEventRecord(ev_split, s1);

    // s2: serial kmeans chain (hi tensor candidates + exact fp32 refine)
    gather_kernel<<<kRC, 128, 0, s2>>>(teacher, ia);
    cnorm_kernel<<<kRC, 128, 0, s2>>>();
    split_cent_hi_kernel<<<(kRC * kD) / (256 * 4), 256, 0, s2>>>();
    cudaStreamWaitEvent(s2, ev_split, 0);
    dim3 ga(kN / 128, kNR), gf(kN / 8, kNR), gp(kCH, kNR * 2), gc(kNC, kNR);
    for (int it = 0; it < kIters; it++) {
        assign_hi_kernel<<<ga, 256, kAsgSmem, s2>>>();
        refine_kernel<<<gf, 256, 0, s2>>>(teacher);
        partial_kernel<<<gp, 256, kPartSmem, s2>>>(teacher);
        combine_kernel<<<gc, 512, 0, s2>>>();
        split_cent_hi_kernel<<<(kRC * kD) / (256 * 4), 256, 0, s2>>>();
    }
    assign_hi_kernel<<<ga, 256, kAsgSmem, s2>>>();
    refine_kernel<<<gf, 256, 0, s2>>>(teacher);
    cudaEventRecord(ev_join, s2);

    // s1: hi-only sim GEMM -> top-32 candidates -> fp32 rescore -> zero out
    dim3 g1(kN / 128, kN / 128);
    gemm_hi_kernel<<<g1, 256, kGemmSmem, s1>>>(out);
    topk32_kernel<<<kN, 256, kTopSmem, s1>>>(out);
    rescore_kernel<<<kN, 256, 0, s1>>>(student, teacher);
    cudaMemsetAsync(d_out, 0, (size_t)kN * kN * sizeof(float), s1);
    cudaEventRecord(ev_main, s1);

    cudaStreamWaitEvent(0, ev_join, 0);
    cudaStreamWaitEvent(0, ev_main, 0);
    scatter_kernel<<<kN * kTK / 256, 256>>>(adj, out);
}

// round 14
// speedup vs baseline: 1.0794x; 1.0325x over previous
#include <cuda_runtime.h>
#include <cstdint>
#include <cstring>
#include <vector>
#include <algorithm>

namespace {
constexpr int kN = 8192, kD = 512, kNC = 64, kNR = 5, kRC = kNC * kNR;
constexpr int kTK = 16, kIters = 20;
constexpr int kCH = 32, kCHP = kN / kCH;   // 32 chunks x 256 points
constexpr int kCand = 32;                  // topk candidate count
constexpr int kTS = 33;                    // topk smem stride (bank-conflict-free)

// ---------------- host-side JAX threefry2x32 ----------------
struct U2 { uint32_t a, b; };
static inline uint32_t rotl32(uint32_t v, int r) { return (v << r) | (v >> (32 - r)); }

static U2 threefry(U2 key, uint32_t x0, uint32_t x1) {
    uint32_t ks0 = key.a, ks1 = key.b, ks2 = key.a ^ key.b ^ 0x1BD11BDAu;
    const int ra[4] = {13, 15, 26, 6}, rb[4] = {17, 29, 16, 24};
    x0 += ks0; x1 += ks1;
    for (int i = 0; i < 4; i++) { x0 += x1; x1 = rotl32(x1, ra[i]); x1 ^= x0; }
    x0 += ks1; x1 += ks2 + 1u;
    for (int i = 0; i < 4; i++) { x0 += x1; x1 = rotl32(x1, rb[i]); x1 ^= x0; }
    x0 += ks2; x1 += ks0 + 2u;
    for (int i = 0; i < 4; i++) { x0 += x1; x1 = rotl32(x1, ra[i]); x1 ^= x0; }
    x0 += ks0; x1 += ks1 + 3u;
    for (int i = 0; i < 4; i++) { x0 += x1; x1 = rotl32(x1, rb[i]); x1 ^= x0; }
    x0 += ks1; x1 += ks2 + 4u;
    for (int i = 0; i < 4; i++) { x0 += x1; x1 = rotl32(x1, ra[i]); x1 ^= x0; }
    x0 += ks2; x1 += ks0 + 5u;
    return {x0, x1};
}

constexpr bool kPartitionable = true;

static void split_keys(U2 key, int n, U2* out) {
    if (kPartitionable) {
        for (int i = 0; i < n; i++) out[i] = threefry(key, 0u, (uint32_t)i);
    } else {
        std::vector<uint32_t> o(2 * n);
        for (int i = 0; i < n; i++) {
            U2 y = threefry(key, (uint32_t)i, (uint32_t)(n + i));
            o[i] = y.a; o[n + i] = y.b;
        }
        for (int j = 0; j < n; j++) out[j] = { o[2 * j], o[2 * j + 1] };
    }
}

static void random_bits32(U2 key, int n, uint32_t* bits) {
    if (kPartitionable) {
        for (int i = 0; i < n; i++) {
            U2 y = threefry(key, 0u, (uint32_t)i);
            bits[i] = y.a ^ y.b;
        }
    } else {
        int h = n / 2;
        for (int i = 0; i < h; i++) {
            U2 y = threefry(key, (uint32_t)i, (uint32_t)(h + i));
            bits[i] = y.a; bits[h + i] = y.b;
        }
    }
}

static void compute_init_indices(int out_idx[kRC]) {
    U2 master{0u, 1234u};
    U2 runkeys[kNR];
    split_keys(master, kNR, runkeys);
    std::vector<int> val(kN), tmp(kN);
    std::vector<uint64_t> kv(kN);
    std::vector<uint32_t> bits(kN);
    for (int r = 0; r < kNR; r++) {
        for (int i = 0; i < kN; i++) val[i] = i;
        U2 cur = runkeys[r];
        for (int round = 0; round < 2; round++) {
            U2 nk[2];
            split_keys(cur, 2, nk);
            cur = nk[0];
            random_bits32(nk[1], kN, bits.data());
            for (int i = 0; i < kN; i++)
                kv[i] = ((uint64_t)bits[i] << 32) | (uint32_t)i;
            std::sort(kv.begin(), kv.end());
            for (int i = 0; i < kN; i++) tmp[i] = val[(uint32_t)(kv[i] & 0xffffffffu)];
            val.swap(tmp);
        }
        for (int c = 0; c < kNC; c++) out_idx[r * kNC + c] = val[c];
    }
}
} // namespace

// ---------------- device scratch ----------------
__device__ float g_cent[kRC * kD];
__device__ float g_cnorm[kRC];
__device__ int   g_labels[kNR * kN];
__device__ int4  g_cand4[kNR * kN];
__device__ int   g_knn[kN * kTK];
__device__ int   g_cand[kN * kCand];
__device__ float g_part[(size_t)kNR * kCH * kNC * kD];
__device__ int   g_pcnt[kNR * kCH * kNC];
__device__ float g_Ahi[(size_t)kN * kD];   // student hi (tf32)
__device__ float g_Bhi[(size_t)kN * kD];   // teacher hi (tf32)
__device__ float g_Chi[(size_t)kRC * kD];  // centroid hi (tf32)

struct IdxArr { int v[kRC]; };

// ---------------- tf32 helpers ----------------
__device__ __forceinline__ float tf32r(float x) {
    uint32_t u; asm("cvt.rna.tf32.f32 %0,%1;" : "=r"(u) : "f"(x));
    return __uint_as_float(u);
}

#define MMA_TF32(d, a, b0, b1) \
    asm volatile( \
        "mma.sync.aligned.m16n8k8.row.col.f32.tf32.tf32.f32 " \
        "{%0,%1,%2,%3}, {%4,%5,%6,%7}, {%8,%9}, {%0,%1,%2,%3};" \
        : "+f"((d)[0]), "+f"((d)[1]), "+f"((d)[2]), "+f"((d)[3]) \
        : "r"((a)[0]), "r"((a)[1]), "r"((a)[2]), "r"((a)[3]), \
          "r"(b0), "r"(b1))

#define CP_ASYNC16(dst, src) \
    asm volatile("cp.async.cg.shared.global [%0], [%1], 16;" :: "r"(dst), "l"(src) : "memory")
#define CP_COMMIT() asm volatile("cp.async.commit_group;" ::: "memory")
#define CP_WAIT1()  asm volatile("cp.async.wait_group 1;" ::: "memory")
#define CP_WAIT0()  asm volatile("cp.async.wait_group 0;" ::: "memory")

namespace {
constexpr int kPitch = 36;
constexpr int kATileB = 128 * kPitch * 4;   // 18432
constexpr int kBTileB = 64 * kPitch * 4;    // 9216
constexpr int kChunks = kD / 32;            // 16
constexpr int kGemmBufB = 2 * kATileB;              // Ahi + Bhi (both 128 rows)
constexpr int kAsgBufB  = kATileB + kBTileB;        // teacher(128) + Chi(64)
}

// ---------------- kernel 0: fp32 -> tf32 hi (inputs) ----------------
__global__ void __launch_bounds__(256) split_hi_kernel(const float* __restrict__ A,
                                                       const float* __restrict__ B)
{
    size_t i = ((size_t)blockIdx.x * 256 + threadIdx.x) * 4;
    float4 a = *reinterpret_cast<const float4*>(A + i);
    float4 b = *reinterpret_cast<const float4*>(B + i);
    float4 ah, bh;
    ah.x = tf32r(a.x); ah.y = tf32r(a.y); ah.z = tf32r(a.z); ah.w = tf32r(a.w);
    bh.x = tf32r(b.x); bh.y = tf32r(b.y); bh.z = tf32r(b.z); bh.w = tf32r(b.w);
    *reinterpret_cast<float4*>(g_Ahi + i) = ah;
    *reinterpret_cast<float4*>(g_Bhi + i) = bh;
}

__global__ void __launch_bounds__(256) split_cent_hi_kernel()
{
    size_t i = ((size_t)blockIdx.x * 256 + threadIdx.x) * 4;
    float4 c = *reinterpret_cast<const float4*>(g_cent + i);
    float4 ch;
    ch.x = tf32r(c.x); ch.y = tf32r(c.y); ch.z = tf32r(c.z); ch.w = tf32r(c.w);
    *reinterpret_cast<float4*>(g_Chi + i) = ch;
}

// ---------------- kernel 1: sim GEMM, hi-only tf32 ----------------
__global__ void __launch_bounds__(256) gemm_hi_kernel(float* __restrict__ C)
{
    extern __shared__ char smem[];
    const int tid = threadIdx.x;
    const int lane = tid & 31, wid = tid >> 5;
    const int wm = wid & 3, wn = wid >> 2;
    const int gm = lane >> 2, gk = lane & 3;
    const int n0 = blockIdx.x * 128, m0 = blockIdx.y * 128;
    const uint32_t sbase = (uint32_t)__cvta_generic_to_shared(smem);

    float acc[2][8][4];
#pragma unroll
    for (int mt = 0; mt < 2; mt++)
#pragma unroll
        for (int nt = 0; nt < 8; nt++)
#pragma unroll
            for (int q = 0; q < 4; q++) acc[mt][nt][q] = 0.f;

    auto copy_chunk = [&](int c, int buf) {
        const int koff = c * 32;
        const uint32_t tb = sbase + (uint32_t)buf * kGemmBufB;
#pragma unroll
        for (int q = 0; q < 4; q++) {
            const int idx = q * 256 + tid;
            const int row = idx >> 3, f4 = idx & 7;
            const uint32_t doff = (uint32_t)(row * kPitch + f4 * 4) * 4;
            CP_ASYNC16(tb + doff, g_Ahi + (size_t)(m0 + row) * kD + koff + f4 * 4);
            CP_ASYNC16(tb + kATileB + doff, g_Bhi + (size_t)(n0 + row) * kD + koff + f4 * 4);
        }
        CP_COMMIT();
    };

    copy_chunk(0, 0);
    copy_chunk(1, 1);

    for (int c = 0; c < kChunks; c++) {
        if (c < kChunks - 1) { CP_WAIT1(); } else { CP_WAIT0(); }
        __syncthreads();
        const int buf = c & 1;
        const float* Ah = reinterpret_cast<const float*>(smem + (size_t)buf * kGemmBufB);
        const float* Bh = reinterpret_cast<const float*>(smem + (size_t)buf * kGemmBufB + kATileB);

#pragma unroll
        for (int kk = 0; kk < 4; kk++) {
            const int kb = kk * 8 + gk;
            uint32_t ah[2][4];
#pragma unroll
            for (int mt = 0; mt < 2; mt++) {
                const int r0 = wm * 32 + mt * 16 + gm;
                ah[mt][0] = __float_as_uint(Ah[r0 * kPitch + kb]);
                ah[mt][1] = __float_as_uint(Ah[(r0 + 8) * kPitch + kb]);
                ah[mt][2] = __float_as_uint(Ah[r0 * kPitch + kb + 4]);
                ah[mt][3] = __float_as_uint(Ah[(r0 + 8) * kPitch + kb + 4]);
            }
#pragma unroll
            for (int nt = 0; nt < 8; nt++) {
                const int rB = wn * 64 + nt * 8 + gm;
                uint32_t bh0 = __float_as_uint(Bh[rB * kPitch + kb]);
                uint32_t bh1 = __float_as_uint(Bh[rB * kPitch + kb + 4]);
                MMA_TF32(acc[0][nt], ah[0], bh0, bh1);
                MMA_TF32(acc[1][nt], ah[1], bh0, bh1);
            }
        }
        __syncthreads();
        if (c + 2 < kChunks) copy_chunk(c + 2, (c + 2) & 1);
    }

#pragma unroll
    for (int mt = 0; mt < 2; mt++) {
#pragma unroll
        for (int nt = 0; nt < 8; nt++) {
            const int r0 = m0 + wm * 32 + mt * 16 + gm;
            const int r1 = r0 + 8;
            const int col = n0 + wn * 64 + nt * 8 + 2 * gk;
            float2 v0, v1;
            v0.x = acc[mt][nt][0] + ((r0 == col) ? 10.f : 0.f);
            v0.y = acc[mt][nt][1] + ((r0 == col + 1) ? 10.f : 0.f);
            v1.x = acc[mt][nt][2] + ((r1 == col) ? 10.f : 0.f);
            v1.y = acc[mt][nt][3] + ((r1 == col + 1) ? 10.f : 0.f);
            *reinterpret_cast<float2*>(&C[(size_t)r0 * kN + col]) = v0;
            *reinterpret_cast<float2*>(&C[(size_t)r1 * kN + col]) = v1;
        }
    }
}

// ---------------- kernel 2: per-row top-32 candidates (stride-33 smem) -------
__device__ __forceinline__ bool beats(float v1, int i1, float v2, int i2) {
    return (v1 > v2) || (v1 == v2 && i1 < i2);
}

__global__ void __launch_bounds__(256) topk32_kernel(const float* __restrict__ sim)
{
    extern __shared__ char smem[];
    float* sv = reinterpret_cast<float*>(smem);                 // [256][33]
    int*   si = reinterpret_cast<int*>(sv + 256 * kTS);         // [256][33]
    const int row = blockIdx.x, t = threadIdx.x;
    float tv[kCand]; int ti[kCand];
#pragma unroll
    for (int k = 0; k < kCand; k++) { tv[k] = -3.402823466e38f; ti[k] = 0x7fffffff; }

    const float* rp = sim + (size_t)row * kN;
    for (int j = t; j < kN; j += 256) {
        float v = rp[j];
        if (beats(v, j, tv[kCand - 1], ti[kCand - 1])) {
            float cv = v; int ci = j;
#pragma unroll
            for (int k = 0; k < kCand; k++) {
                if (beats(cv, ci, tv[k], ti[k])) {
                    float fv = tv[k]; int fi = ti[k];
                    tv[k] = cv; ti[k] = ci; cv = fv; ci = fi;
                }
            }
        }
    }
#pragma unroll
    for (int k = 0; k < kCand; k++) { sv[t * kTS + k] = tv[k]; si[t * kTS + k] = ti[k]; }
    __syncthreads();

    for (int s = 128; s >= 1; s >>= 1) {
        if (t < s) {
            float mv[kCand]; int mi[kCand];
            int ia = 0, ib = 0;
#pragma unroll
            for (int k = 0; k < kCand; k++) {
                float av = sv[t * kTS + ia], bw = sv[(t + s) * kTS + ib];
                int   ai = si[t * kTS + ia], bj = si[(t + s) * kTS + ib];
                bool ta = beats(av, ai, bw, bj);
                mv[k] = ta ? av : bw; mi[k] = ta ? ai : bj;
                if (ta) ia++; else ib++;
            }
#pragma unroll
            for (int k = 0; k < kCand; k++) { sv[t * kTS + k] = mv[k]; si[t * kTS + k] = mi[k]; }
        }
        __syncthreads();
    }
    if (t < kCand) g_cand[row * kCand + t] = si[t];
}

// ---------------- kernel 2b: fp32 rescore of candidates -> exact top-16 ------
__global__ void __launch_bounds__(256) rescore_kernel(const float* __restrict__ S,
                                                      const float* __restrict__ T)
{
    __shared__ float cv[kCand];
    __shared__ int   ci[kCand];
    const int row = blockIdx.x;
    const int tid = threadIdx.x;
    const int wid = tid >> 5, lane = tid & 31;

#pragma unroll
    for (int k = 0; k < 4; k++) {
        const int slot = wid + 8 * k;
        const int cand = g_cand[row * kCand + slot];
        float s = 0.f;
#pragma unroll
        for (int u = 0; u < 16; u++)
            s = fmaf(S[(size_t)row * kD + u * 32 + lane],
                     T[(size_t)cand * kD + u * 32 + lane], s);
#pragma unroll
        for (int m = 16; m >= 1; m >>= 1) s += __shfl_xor_sync(0xffffffffu, s, m);
        if (lane == 0) {
            if (cand == row) s += 10.f;
            cv[slot] = s; ci[slot] = cand;
        }
    }
    __syncthreads();
    if (tid == 0) {
        unsigned used = 0;
        for (int k = 0; k < kTK; k++) {
            float bv = -3.402823466e38f; int bi = 0x7fffffff, bs = -1;
            for (int q = 0; q < kCand; q++) {
                if (used & (1u << q)) continue;
                if (beats(cv[q], ci[q], bv, bi)) { bv = cv[q]; bi = ci[q]; bs = q; }
            }
            used |= (1u << bs);
            g_knn[row * kTK + k] = bi;
        }
    }
}

// ---------------- kernel 3/4: gather + norms ----------------
__global__ void gather_kernel(const float* __restrict__ X, IdxArr ia)
{
    int b = blockIdx.x;
    int src = ia.v[b];
    for (int d = threadIdx.x; d < kD; d += blockDim.x)
        g_cent[(size_t)b * kD + d] = X[(size_t)src * kD + d];
}

__global__ void __launch_bounds__(128) cnorm_kernel()
{
    int rc = blockIdx.x;
    float s = 0.f;
    for (int d = threadIdx.x; d < kD; d += 128) {
        float v = g_cent[(size_t)rc * kD + d];
        s = fmaf(v, v, s);
    }
#pragma unroll
    for (int m = 16; m >= 1; m >>= 1) s += __shfl_xor_sync(0xffffffffu, s, m);
    __shared__ float red[4];
    if ((threadIdx.x & 31) == 0) red[threadIdx.x >> 5] = s;
    __syncthreads();
    if (threadIdx.x == 0) g_cnorm[rc] = red[0] + red[1] + red[2] + red[3];
}

// ---------------- kernel 5: assign hi-only -> top-4 candidates ----------------
__device__ __forceinline__ bool better(float v, int i, float bv, int bi) {
    return (v < bv) || (v == bv && i < bi);
}

__global__ void __launch_bounds__(256) assign_hi_kernel()
{
    extern __shared__ char smem[];
    __shared__ float cns[kNC];
    __shared__ float sd4[2][128][4];
    __shared__ int   si4[2][128][4];

    const int tid = threadIdx.x;
    const int lane = tid & 31, wid = tid >> 5;
    const int wm = wid & 3, wn = wid >> 2;
    const int gm = lane >> 2, gk = lane & 3;
    const int m0 = blockIdx.x * 128;
    const int r  = blockIdx.y;
    const uint32_t sbase = (uint32_t)__cvta_generic_to_shared(smem);
    const size_t cbase = (size_t)r * kNC * kD;

    if (tid < kNC) cns[tid] = g_cnorm[r * kNC + tid];

    float acc[2][4][4];
#pragma unroll
    for (int mt = 0; mt < 2; mt++)
#pragma unroll
        for (int nt = 0; nt < 4; nt++)
#pragma unroll
            for (int q = 0; q < 4; q++) acc[mt][nt][q] = 0.f;

    auto copy_chunk = [&](int c, int buf) {
        const int koff = c * 32;
        const uint32_t tb = sbase + (uint32_t)buf * kAsgBufB;
#pragma unroll
        for (int q = 0; q < 4; q++) {
            const int idx = q * 256 + tid;
            const int row = idx >> 3, f4 = idx & 7;
            const uint32_t doff = (uint32_t)(row * kPitch + f4 * 4) * 4;
            CP_ASYNC16(tb + doff, g_Bhi + (size_t)(m0 + row) * kD + koff + f4 * 4);
        }
#pragma unroll
        for (int q = 0; q < 2; q++) {
            const int idx = q * 256 + tid;
            const int row = idx >> 3, f4 = idx & 7;
            const uint32_t doff = (uint32_t)(row * kPitch + f4 * 4) * 4;
            CP_ASYNC16(tb + kATileB + doff, g_Chi + cbase + (size_t)row * kD + koff + f4 * 4);
        }
        CP_COMMIT();
    };

    copy_chunk(0, 0);
    copy_chunk(1, 1);

    for (int c = 0; c < kChunks; c++) {
        if (c < kChunks - 1) { CP_WAIT1(); } else { CP_WAIT0(); }
        __syncthreads();
        const int buf = c & 1;
        const float* Ah = reinterpret_cast<const float*>(smem + (size_t)buf * kAsgBufB);
        const float* Bh = reinterpret_cast<const float*>(smem + (size_t)buf * kAsgBufB + kATileB);

#pragma unroll
        for (int kk = 0; kk < 4; kk++) {
            const int kb = kk * 8 + gk;
            uint32_t ah[2][4];
#pragma unroll
            for (int mt = 0; mt < 2; mt++) {
                const int r0 = wm * 32 + mt * 16 + gm;
                ah[mt][0] = __float_as_uint(Ah[r0 * kPitch + kb]);
                ah[mt][1] = __float_as_uint(Ah[(r0 + 8) * kPitch + kb]);
                ah[mt][2] = __float_as_uint(Ah[r0 * kPitch + kb + 4]);
                ah[mt][3] = __float_as_uint(Ah[(r0 + 8) * kPitch + kb + 4]);
            }
#pragma unroll
            for (int nt = 0; nt < 4; nt++) {
                const int rB = wn * 32 + nt * 8 + gm;
                uint32_t bh0 = __float_as_uint(Bh[rB * kPitch + kb]);
                uint32_t bh1 = __float_as_uint(Bh[rB * kPitch + kb + 4]);
                MMA_TF32(acc[0][nt], ah[0], bh0, bh1);
                MMA_TF32(acc[1][nt], ah[1], bh0, bh1);
            }
        }
        __syncthreads();
        if (c + 2 < kChunks) copy_chunk(c + 2, (c + 2) & 1);
    }

    // top-4 candidates per point
#pragma unroll
    for (int mt = 0; mt < 2; mt++) {
#pragma unroll
        for (int half = 0; half < 2; half++) {
            float tv[4]; int ti[4];
#pragma unroll
            for (int q = 0; q < 4; q++) { tv[q] = 3.402823466e38f; ti[q] = 0x7fffffff; }
#pragma unroll
            for (int nt = 0; nt < 4; nt++) {
                const int c0 = wn * 32 + nt * 8 + 2 * gk;
#pragma unroll
                for (int hh = 0; hh < 2; hh++) {
                    float v = cns[c0 + hh] - 2.f * acc[mt][nt][half * 2 + hh];
                    int   i = c0 + hh;
                    if (better(v, i, tv[3], ti[3])) {
                        float cvv = v; int cii = i;
#pragma unroll
                        for (int q = 0; q < 4; q++) {
                            if (better(cvv, cii, tv[q], ti[q])) {
                                float fv = tv[q]; int fi = ti[q];
                                tv[q] = cvv; ti[q] = cii; cvv = fv; cii = fi;
                            }
                        }
                    }
                }
            }
#pragma unroll
            for (int m = 1; m < 4; m <<= 1) {
                float ov[4]; int oi[4];
#pragma unroll
                for (int q = 0; q < 4; q++) {
                    ov[q] = __shfl_xor_sync(0xffffffffu, tv[q], m);
                    oi[q] = __shfl_xor_sync(0xffffffffu, ti[q], m);
                }
                float mv[4]; int mi[4];
                int ia = 0, ib = 0;
#pragma unroll
                for (int q = 0; q < 4; q++) {
                    bool ta = better(tv[ia], ti[ia], ov[ib], oi[ib]);
                    mv[q] = ta ? tv[ia] : ov[ib];
                    mi[q] = ta ? ti[ia] : oi[ib];
                    if (ta) ia++; else ib++;
                }
#pragma unroll
                for (int q = 0; q < 4; q++) { tv[q] = mv[q]; ti[q] = mi[q]; }
            }
            if (gk == 0) {
                const int rl = wm * 32 + mt * 16 + half * 8 + gm;
#pragma unroll
                for (int q = 0; q < 4; q++) { sd4[wn][rl][q] = tv[q]; si4[wn][rl][q] = ti[q]; }
            }
        }
    }
    __syncthreads();
    if (tid < 128) {
        float mv[4]; int mi[4];
        int ia = 0, ib = 0;
#pragma unroll
        for (int q = 0; q < 4; q++) {
            bool ta = better(sd4[0][tid][ia], si4[0][tid][ia], sd4[1][tid][ib], si4[1][tid][ib]);
            mv[q] = ta ? sd4[0][tid][ia] : sd4[1][tid][ib];
            mi[q] = ta ? si4[0][tid][ia] : si4[1][tid][ib];
            if (ta) ia++; else ib++;
        }
        (void)mv;
        g_cand4[r * kN + m0 + tid] = make_int4(mi[0], mi[1], mi[2], mi[3]);
    }
}

// ---------------- kernel 5b: exact fp32 refine (all runs per launch) ---------
__global__ void __launch_bounds__(256) refine_kernel(const float* __restrict__ X)
{
    const int wid = threadIdx.x >> 5, lane = threadIdx.x & 31;
    const int p = blockIdx.x * 8 + wid;

    float x[16];
#pragma unroll
    for (int u = 0; u < 16; u++) x[u] = X[(size_t)p * kD + u * 32 + lane];

#pragma unroll
    for (int r = 0; r < kNR; r++) {
        const int4 cd = g_cand4[r * kN + p];
        const int cands[4] = {cd.x, cd.y, cd.z, cd.w};
        const float* C = g_cent + (size_t)r * kNC * kD;
        float bv = 3.402823466e38f; int bi = 0x7fffffff;
#pragma unroll
        for (int q = 0; q < 4; q++) {
            const int c = cands[q];
            float s = 0.f;
#pragma unroll
            for (int u = 0; u < 16; u++) s = fmaf(x[u], C[(size_t)c * kD + u * 32 + lane], s);
#pragma unroll
            for (int m = 16; m >= 1; m >>= 1) s += __shfl_xor_sync(0xffffffffu, s, m);
            float v = g_cnorm[r * kNC + c] - 2.f * s;
            if (better(v, c, bv, bi)) { bv = v; bi = c; }
        }
        if (lane == 0) g_labels[r * kN + p] = bi;
    }
}

// ---------------- kernel 6a: point-centric partial sums (d-split) ------------
__global__ void __launch_bounds__(256) partial_kernel(const float* __restrict__ X)
{
    extern __shared__ float sm[];
    float* ssum = sm;                            // [kNC][256]
    int*   slab = (int*)(sm + kNC * 256);        // [kCHP]
    int*   scnt = (int*)(sm + kNC * 256) + kCHP; // [kNC]

    const int ch = blockIdx.x;
    const int r  = blockIdx.y >> 1, dh = blockIdx.y & 1;
    const int t = threadIdx.x;
    const int d = dh * 256 + t;
    const int p0 = ch * kCHP;
    const int* lab = g_labels + r * kN;

#pragma unroll
    for (int c = 0; c < kNC; c++) ssum[c * 256 + t] = 0.f;
    if (t < kNC) scnt[t] = 0;
    slab[t] = lab[p0 + t];
    __syncthreads();
    if (dh == 0) atomicAdd(&scnt[slab[t]], 1);
    __syncthreads();

    for (int i = 0; i < kCHP; i += 8) {
        float x0 = X[(size_t)(p0 + i + 0) * kD + d];
        float x1 = X[(size_t)(p0 + i + 1) * kD + d];
        float x2 = X[(size_t)(p0 + i + 2) * kD + d];
        float x3 = X[(size_t)(p0 + i + 3) * kD + d];
        float x4 = X[(size_t)(p0 + i + 4) * kD + d];
        float x5 = X[(size_t)(p0 + i + 5) * kD + d];
        float x6 = X[(size_t)(p0 + i + 6) * kD + d];
        float x7 = X[(size_t)(p0 + i + 7) * kD + d];
        int c0 = slab[i + 0], c1 = slab[i + 1], c2 = slab[i + 2], c3 = slab[i + 3];
        int c4 = slab[i + 4], c5 = slab[i + 5], c6 = slab[i + 6], c7 = slab[i + 7];
        ssum[c0 * 256 + t] += x0;
        ssum[c1 * 256 + t] += x1;
        ssum[c2 * 256 + t] += x2;
        ssum[c3 * 256 + t] += x3;
        ssum[c4 * 256 + t] += x4;
        ssum[c5 * 256 + t] += x5;
        ssum[c6 * 256 + t] += x6;
        ssum[c7 * 256 + t] += x7;
    }
    __syncthreads();

    const size_t base = (size_t)(r * kCH + ch) * kNC;
#pragma unroll
    for (int c = 0; c < kNC; c++)
        g_part[(base + c) * kD + d] = ssum[c * 256 + t];
    if (dh == 0 && t < kNC) g_pcnt[base + t] = scnt[t];
}

// ---------------- kernel 6b: combine partials -> centroid + norm -------------
__global__ void __launch_bounds__(512) combine_kernel()
{
    __shared__ float fred[16];
    const int c = blockIdx.x, r = blockIdx.y;
    const int t = threadIdx.x;
    const unsigned lane = t & 31;

    int cnt = 0;
    float sum = 0.f;
#pragma unroll
    for (int ch = 0; ch < kCH; ch++) {
        size_t base = (size_t)(r * kCH + ch) * kNC + c;
        cnt += g_pcnt[base];
        sum += g_part[base * kD + t];
    }
    const int rc = r * kNC + c;
    float oldc = g_cent[(size_t)rc * kD + t];
    float newc = (cnt > 0) ? (sum / (float)cnt) : oldc;
    g_cent[(size_t)rc * kD + t] = newc;

    float sq = newc * newc;
#pragma unroll
    for (int m = 16; m >= 1; m >>= 1) sq += __shfl_xor_sync(0xffffffffu, sq, m);
    if (lane == 0) fred[t >> 5] = sq;
    __syncthreads();
    if (t == 0) {
        float s = 0.f;
        for (int w = 0; w < 16; w++) s += fred[w];
        g_cnorm[rc] = s;
    }
}

// ---------------- kernel 7: scatter final output ----------------
__global__ void __launch_bounds__(256) scatter_kernel(
    const float* __restrict__ adj, float* __restrict__ out)
{
    int e = blockIdx.x * blockDim.x + threadIdx.x;
    int i = e >> 4;
    int j = g_knn[e];
    float v = adj[(size_t)i * kN + j];
    bool m = false;
#pragma unroll
    for (int r = 0; r < kNR; r++)
        m |= (g_labels[r * kN + i] == g_labels[r * kN + j]);
    out[(size_t)i * kN + j] = v + (m ? 1.f : 0.f);
}

// ---------------- launcher ----------------
extern "C" void kernel_launch(void* const* d_in, const int* in_sizes, int n_in,
                              void* d_out, int out_size)
{
    (void)in_sizes; (void)n_in; (void)out_size;
    const float* adj     = (const float*)d_in[0];
    const float* student = (const float*)d_in[1];
    const float* teacher = (const float*)d_in[2];
    float* out = (float*)d_out;

    constexpr size_t kPartSmem = (size_t)kNC * 256 * 4 + kCHP * 4 + kNC * 4;
    constexpr size_t kGemmSmem = 2 * (size_t)kGemmBufB;   // 73.7 KB
    constexpr size_t kAsgSmem  = 2 * (size_t)kAsgBufB;    // 55.3 KB
    constexpr size_t kTopSmem  = 256 * kTS * 8;           // 67.6 KB
    static cudaStream_t s2 = nullptr, s1 = nullptr;
    static cudaEvent_t ev_fork = nullptr, ev_join = nullptr, ev_main = nullptr, ev_split = nullptr;
    if (!s2) {
        int lo, hi;
        cudaDeviceGetStreamPriorityRange(&lo, &hi);
        cudaStreamCreateWithPriority(&s2, cudaStreamNonBlocking, hi);
        cudaStreamCreateWithPriority(&s1, cudaStreamNonBlocking, lo);
        cudaEventCreateWithFlags(&ev_fork, cudaEventDisableTiming);
        cudaEventCreateWithFlags(&ev_join, cudaEventDisableTiming);
        cudaEventCreateWithFlags(&ev_main, cudaEventDisableTiming);
        cudaEventCreateWithFlags(&ev_split, cudaEventDisableTiming);
        cudaFuncSetAttribute(partial_kernel,
                             cudaFuncAttributeMaxDynamicSharedMemorySize, (int)kPartSmem);
        cudaFuncSetAttribute(gemm_hi_kernel,
                             cudaFuncAttributeMaxDynamicSharedMemorySize, (int)kGemmSmem);
        cudaFuncSetAttribute(assign_hi_kernel,
                             cudaFuncAttributeMaxDynamicSharedMemorySize, (int)kAsgSmem);
        cudaFuncSetAttribute(topk32_kernel,
                             cudaFuncAttributeMaxDynamicSharedMemorySize, (int)kTopSmem);
    }

    IdxArr ia;
    compute_init_indices(ia.v);

    cudaEventRecord(ev_fork, 0);
    cudaStreamWaitEvent(s2, ev_fork, 0);
    cudaStreamWaitEvent(s1, ev_fork, 0);

    // s1: tf32 hi split (also feeds assign's teacher tiles)
    split_hi_kernel<<<(kN * kD) / (256 * 4), 256, 0, s1>>>(student, teacher);
    cudaEventRecord(ev_split, s1);

    // s2: serial kmeans chain (hi tensor candidates + exact fp32 refine)
    gather_kernel<<<kRC, 128, 0, s2>>>(teacher, ia);
    cnorm_kernel<<<kRC, 128, 0, s2>>>();
    split_cent_hi_kernel<<<(kRC * kD) / (256 * 4), 256, 0, s2>>>();
    cudaStreamWaitEvent(s2, ev_split, 0);
    dim3 ga(kN / 128, kNR), gp(kCH, kNR * 2), gc(kNC, kNR);
    for (int it = 0; it < kIters; it++) {
        assign_hi_kernel<<<ga, 256, kAsgSmem, s2>>>();
        refine_kernel<<<kN / 8, 256, 0, s2>>>(teacher);
        partial_kernel<<<gp, 256, kPartSmem, s2>>>(teacher);
        combine_kernel<<<gc, 512, 0, s2>>>();
        split_cent_hi_kernel<<<(kRC * kD) / (256 * 4), 256, 0, s2>>>();
    }
    assign_hi_kernel<<<ga, 256, kAsgSmem, s2>>>();
    refine_kernel<<<kN / 8, 256, 0, s2>>>(teacher);
    cudaEventRecord(ev_join, s2);

    // s1: hi-only sim GEMM -> top-32 candidates -> fp32 rescore -> zero out
    dim3 g1(kN / 128, kN / 128);
    gemm_hi_kernel<<<g1, 256, kGemmSmem, s1>>>(out);
    topk32_kernel<<<kN, 256, kTopSmem, s1>>>(out);
    rescore_kernel<<<kN, 256, 0, s1>>>(student, teacher);
    cudaMemsetAsync(d_out, 0, (size_t)kN * kN * sizeof(float), s1);
    cudaEventRecord(ev_main, s1);

    cudaStreamWaitEvent(0, ev_join, 0);
    cudaStreamWaitEvent(0, ev_main, 0);
    scatter_kernel<<<kN * kTK / 256, 256>>>(adj, out);
}

// round 15
// speedup vs baseline: 1.6928x; 1.5683x over previous
#include <cuda_runtime.h>
#include <cstdint>
#include <cstring>
#include <vector>
#include <algorithm>

namespace {
constexpr int kN = 8192, kD = 512, kNC = 64, kNR = 5, kRC = kNC * kNR;
constexpr int kTK = 16, kIters = 20;
constexpr int kCH = 32, kCHP = kN / kCH;   // 32 chunks x 256 points
constexpr int kTS = 17;                    // topk16 smem stride (conflict-free)

// ---------------- host-side JAX threefry2x32 ----------------
struct U2 { uint32_t a, b; };
static inline uint32_t rotl32(uint32_t v, int r) { return (v << r) | (v >> (32 - r)); }

static U2 threefry(U2 key, uint32_t x0, uint32_t x1) {
    uint32_t ks0 = key.a, ks1 = key.b, ks2 = key.a ^ key.b ^ 0x1BD11BDAu;
    const int ra[4] = {13, 15, 26, 6}, rb[4] = {17, 29, 16, 24};
    x0 += ks0; x1 += ks1;
    for (int i = 0; i < 4; i++) { x0 += x1; x1 = rotl32(x1, ra[i]); x1 ^= x0; }
    x0 += ks1; x1 += ks2 + 1u;
    for (int i = 0; i < 4; i++) { x0 += x1; x1 = rotl32(x1, rb[i]); x1 ^= x0; }
    x0 += ks2; x1 += ks0 + 2u;
    for (int i = 0; i < 4; i++) { x0 += x1; x1 = rotl32(x1, ra[i]); x1 ^= x0; }
    x0 += ks0; x1 += ks1 + 3u;
    for (int i = 0; i < 4; i++) { x0 += x1; x1 = rotl32(x1, rb[i]); x1 ^= x0; }
    x0 += ks1; x1 += ks2 + 4u;
    for (int i = 0; i < 4; i++) { x0 += x1; x1 = rotl32(x1, ra[i]); x1 ^= x0; }
    x0 += ks2; x1 += ks0 + 5u;
    return {x0, x1};
}

constexpr bool kPartitionable = true;

static void split_keys(U2 key, int n, U2* out) {
    if (kPartitionable) {
        for (int i = 0; i < n; i++) out[i] = threefry(key, 0u, (uint32_t)i);
    } else {
        std::vector<uint32_t> o(2 * n);
        for (int i = 0; i < n; i++) {
            U2 y = threefry(key, (uint32_t)i, (uint32_t)(n + i));
            o[i] = y.a; o[n + i] = y.b;
        }
        for (int j = 0; j < n; j++) out[j] = { o[2 * j], o[2 * j + 1] };
    }
}

static void random_bits32(U2 key, int n, uint32_t* bits) {
    if (kPartitionable) {
        for (int i = 0; i < n; i++) {
            U2 y = threefry(key, 0u, (uint32_t)i);
            bits[i] = y.a ^ y.b;
        }
    } else {
        int h = n / 2;
        for (int i = 0; i < h; i++) {
            U2 y = threefry(key, (uint32_t)i, (uint32_t)(h + i));
            bits[i] = y.a; bits[h + i] = y.b;
        }
    }
}

static void compute_init_indices(int out_idx[kRC]) {
    U2 master{0u, 1234u};
    U2 runkeys[kNR];
    split_keys(master, kNR, runkeys);
    std::vector<int> val(kN), tmp(kN);
    std::vector<uint64_t> kv(kN);
    std::vector<uint32_t> bits(kN);
    for (int r = 0; r < kNR; r++) {
        for (int i = 0; i < kN; i++) val[i] = i;
        U2 cur = runkeys[r];
        for (int round = 0; round < 2; round++) {
            U2 nk[2];
            split_keys(cur, 2, nk);
            cur = nk[0];
            random_bits32(nk[1], kN, bits.data());
            for (int i = 0; i < kN; i++)
                kv[i] = ((uint64_t)bits[i] << 32) | (uint32_t)i;
            std::sort(kv.begin(), kv.end());
            for (int i = 0; i < kN; i++) tmp[i] = val[(uint32_t)(kv[i] & 0xffffffffu)];
            val.swap(tmp);
        }
        for (int c = 0; c < kNC; c++) out_idx[r * kNC + c] = val[c];
    }
}
} // namespace

// ---------------- device scratch ----------------
__device__ float g_cent[kRC * kD];
__device__ float g_cnorm[kRC];
__device__ int   g_labels[kNR * kN];
__device__ int4  g_cand4[kNR * kN];
__device__ int   g_knn[kN * kTK];
__device__ float g_part[(size_t)kNR * kCH * kNC * kD];
__device__ int   g_pcnt[kNR * kCH * kNC];
__device__ float g_Ahi[(size_t)kN * kD];   // student hi/lo (tf32 split)
__device__ float g_Alo[(size_t)kN * kD];
__device__ float g_Bhi[(size_t)kN * kD];   // teacher hi/lo
__device__ float g_Blo[(size_t)kN * kD];
__device__ float g_Chi[(size_t)kRC * kD];  // centroid hi

struct IdxArr { int v[kRC]; };

// ---------------- tf32 helpers ----------------
__device__ __forceinline__ float tf32r(float x) {
    uint32_t u; asm("cvt.rna.tf32.f32 %0,%1;" : "=r"(u) : "f"(x));
    return __uint_as_float(u);
}

#define MMA_TF32(d, a, b0, b1) \
    asm volatile( \
        "mma.sync.aligned.m16n8k8.row.col.f32.tf32.tf32.f32 " \
        "{%0,%1,%2,%3}, {%4,%5,%6,%7}, {%8,%9}, {%0,%1,%2,%3};" \
        : "+f"((d)[0]), "+f"((d)[1]), "+f"((d)[2]), "+f"((d)[3]) \
        : "r"((a)[0]), "r"((a)[1]), "r"((a)[2]), "r"((a)[3]), \
          "r"(b0), "r"(b1))

#define CP_ASYNC16(dst, src) \
    asm volatile("cp.async.cg.shared.global [%0], [%1], 16;" :: "r"(dst), "l"(src) : "memory")
#define CP_COMMIT() asm volatile("cp.async.commit_group;" ::: "memory")
#define CP_WAIT1()  asm volatile("cp.async.wait_group 1;" ::: "memory")
#define CP_WAIT0()  asm volatile("cp.async.wait_group 0;" ::: "memory")

namespace {
constexpr int kPitch = 36;
constexpr int kTileB = 128 * kPitch * 4;    // 18432
constexpr int kBTileB = 64 * kPitch * 4;    // 9216
constexpr int kChunks = kD / 32;            // 16
constexpr int kAsgBufB = kTileB + kBTileB;  // teacher(128) + Chi(64) = 27648
}

// ---------------- kernel 0: fp32 -> tf32 hi/lo (inputs) ----------------
__device__ __forceinline__ void split1(float x, float& h, float& l) {
    h = tf32r(x);
    l = tf32r(x - h);
}

__global__ void __launch_bounds__(256) split_kernel(const float* __restrict__ A,
                                                    const float* __restrict__ B)
{
    size_t i = ((size_t)blockIdx.x * 256 + threadIdx.x) * 4;
    float4 a = *reinterpret_cast<const float4*>(A + i);
    float4 b = *reinterpret_cast<const float4*>(B + i);
    float4 ah, al, bh, bl;
    split1(a.x, ah.x, al.x); split1(a.y, ah.y, al.y);
    split1(a.z, ah.z, al.z); split1(a.w, ah.w, al.w);
    split1(b.x, bh.x, bl.x); split1(b.y, bh.y, bl.y);
    split1(b.z, bh.z, bl.z); split1(b.w, bh.w, bl.w);
    *reinterpret_cast<float4*>(g_Ahi + i) = ah;
    *reinterpret_cast<float4*>(g_Alo + i) = al;
    *reinterpret_cast<float4*>(g_Bhi + i) = bh;
    *reinterpret_cast<float4*>(g_Blo + i) = bl;
}

__global__ void __launch_bounds__(256) split_cent_hi_kernel()
{
    size_t i = ((size_t)blockIdx.x * 256 + threadIdx.x) * 4;
    float4 c = *reinterpret_cast<const float4*>(g_cent + i);
    float4 ch;
    ch.x = tf32r(c.x); ch.y = tf32r(c.y); ch.z = tf32r(c.z); ch.w = tf32r(c.w);
    *reinterpret_cast<float4*>(g_Chi + i) = ch;
}

// ---------------- kernel 1: sim GEMM via mma.sync 3xTF32 (R11, proven) -------
__global__ void __launch_bounds__(256) gemm_mma_kernel(float* __restrict__ C)
{
    extern __shared__ char smem[];
    const int tid = threadIdx.x;
    const int lane = tid & 31, wid = tid >> 5;
    const int wm = wid & 3, wn = wid >> 2;
    const int gm = lane >> 2, gk = lane & 3;
    const int n0 = blockIdx.x * 128, m0 = blockIdx.y * 128;
    const uint32_t sbase = (uint32_t)__cvta_generic_to_shared(smem);

    float acc[2][8][4];
#pragma unroll
    for (int mt = 0; mt < 2; mt++)
#pragma unroll
        for (int nt = 0; nt < 8; nt++)
#pragma unroll
            for (int q = 0; q < 4; q++) acc[mt][nt][q] = 0.f;

    int srow[4], sf4[4];
#pragma unroll
    for (int q = 0; q < 4; q++) {
        int idx = q * 256 + tid;
        srow[q] = idx >> 3;
        sf4[q]  = idx & 7;
    }

    auto copy_chunk = [&](int c, int buf) {
        const int koff = c * 32;
        const uint32_t tb = sbase + (uint32_t)buf * 4 * kTileB;
#pragma unroll
        for (int q = 0; q < 4; q++) {
            const int row = srow[q], f4 = sf4[q];
            const uint32_t doff = (uint32_t)(row * kPitch + f4 * 4) * 4;
            const size_t gA = (size_t)(m0 + row) * kD + koff + f4 * 4;
            const size_t gB = (size_t)(n0 + row) * kD + koff + f4 * 4;
            CP_ASYNC16(tb + 0 * kTileB + doff, g_Ahi + gA);
            CP_ASYNC16(tb + 1 * kTileB + doff, g_Alo + gA);
            CP_ASYNC16(tb + 2 * kTileB + doff, g_Bhi + gB);
            CP_ASYNC16(tb + 3 * kTileB + doff, g_Blo + gB);
        }
        CP_COMMIT();
    };

    copy_chunk(0, 0);
    copy_chunk(1, 1);

    for (int c = 0; c < kChunks; c++) {
        if (c < kChunks - 1) { CP_WAIT1(); } else { CP_WAIT0(); }
        __syncthreads();
        const int buf = c & 1;
        const float* Ah = reinterpret_cast<const float*>(smem + (size_t)(buf * 4 + 0) * kTileB);
        const float* Al = reinterpret_cast<const float*>(smem + (size_t)(buf * 4 + 1) * kTileB);
        const float* Bh = reinterpret_cast<const float*>(smem + (size_t)(buf * 4 + 2) * kTileB);
        const float* Bl = reinterpret_cast<const float*>(smem + (size_t)(buf * 4 + 3) * kTileB);

#pragma unroll
        for (int kk = 0; kk < 4; kk++) {
            const int kb = kk * 8 + gk;
            uint32_t ah[2][4], al[2][4];
#pragma unroll
            for (int mt = 0; mt < 2; mt++) {
                const int r0 = wm * 32 + mt * 16 + gm;
                ah[mt][0] = __float_as_uint(Ah[r0 * kPitch + kb]);
                ah[mt][1] = __float_as_uint(Ah[(r0 + 8) * kPitch + kb]);
                ah[mt][2] = __float_as_uint(Ah[r0 * kPitch + kb + 4]);
                ah[mt][3] = __float_as_uint(Ah[(r0 + 8) * kPitch + kb + 4]);
                al[mt][0] = __float_as_uint(Al[r0 * kPitch + kb]);
                al[mt][1] = __float_as_uint(Al[(r0 + 8) * kPitch + kb]);
                al[mt][2] = __float_as_uint(Al[r0 * kPitch + kb + 4]);
                al[mt][3] = __float_as_uint(Al[(r0 + 8) * kPitch + kb + 4]);
            }
#pragma unroll
            for (int nt = 0; nt < 8; nt++) {
                const int rB = wn * 64 + nt * 8 + gm;
                uint32_t bh0 = __float_as_uint(Bh[rB * kPitch + kb]);
                uint32_t bh1 = __float_as_uint(Bh[rB * kPitch + kb + 4]);
                uint32_t bl0 = __float_as_uint(Bl[rB * kPitch + kb]);
                uint32_t bl1 = __float_as_uint(Bl[rB * kPitch + kb + 4]);
                MMA_TF32(acc[0][nt], ah[0], bh0, bh1);
                MMA_TF32(acc[1][nt], ah[1], bh0, bh1);
                MMA_TF32(acc[0][nt], ah[0], bl0, bl1);
                MMA_TF32(acc[1][nt], ah[1], bl0, bl1);
                MMA_TF32(acc[0][nt], al[0], bh0, bh1);
                MMA_TF32(acc[1][nt], al[1], bh0, bh1);
            }
        }
        __syncthreads();
        if (c + 2 < kChunks) copy_chunk(c + 2, (c + 2) & 1);
    }

#pragma unroll
    for (int mt = 0; mt < 2; mt++) {
#pragma unroll
        for (int nt = 0; nt < 8; nt++) {
            const int r0 = m0 + wm * 32 + mt * 16 + gm;
            const int r1 = r0 + 8;
            const int col = n0 + wn * 64 + nt * 8 + 2 * gk;
            float2 v0, v1;
            v0.x = acc[mt][nt][0] + ((r0 == col) ? 10.f : 0.f);
            v0.y = acc[mt][nt][1] + ((r0 == col + 1) ? 10.f : 0.f);
            v1.x = acc[mt][nt][2] + ((r1 == col) ? 10.f : 0.f);
            v1.y = acc[mt][nt][3] + ((r1 == col + 1) ? 10.f : 0.f);
            *reinterpret_cast<float2*>(&C[(size_t)r0 * kN + col]) = v0;
            *reinterpret_cast<float2*>(&C[(size_t)r1 * kN + col]) = v1;
        }
    }
}

// ---------------- kernel 2: per-row top-16 (stride-17, conflict-free) --------
__device__ __forceinline__ bool beats(float v1, int i1, float v2, int i2) {
    return (v1 > v2) || (v1 == v2 && i1 < i2);
}

__global__ void __launch_bounds__(256) topk_kernel(const float* __restrict__ sim)
{
    __shared__ float sv[256 * kTS];
    __shared__ int   si[256 * kTS];
    const int row = blockIdx.x, t = threadIdx.x;
    float tv[16]; int ti[16];
#pragma unroll
    for (int k = 0; k < 16; k++) { tv[k] = -3.402823466e38f; ti[k] = 0x7fffffff; }

    const float* rp = sim + (size_t)row * kN;
    for (int j = t; j < kN; j += 256) {
        float v = rp[j];
        if (beats(v, j, tv[15], ti[15])) {
            float cv = v; int ci = j;
#pragma unroll
            for (int k = 0; k < 16; k++) {
                if (beats(cv, ci, tv[k], ti[k])) {
                    float fv = tv[k]; int fi = ti[k];
                    tv[k] = cv; ti[k] = ci; cv = fv; ci = fi;
                }
            }
        }
    }
#pragma unroll
    for (int k = 0; k < 16; k++) { sv[t * kTS + k] = tv[k]; si[t * kTS + k] = ti[k]; }
    __syncthreads();

    for (int s = 128; s >= 1; s >>= 1) {
        if (t < s) {
            float mv[16]; int mi[16];
            int ia = 0, ib = 0;
#pragma unroll
            for (int k = 0; k < 16; k++) {
                float av = sv[t * kTS + ia], bw = sv[(t + s) * kTS + ib];
                int   ai = si[t * kTS + ia], bj = si[(t + s) * kTS + ib];
                bool ta = beats(av, ai, bw, bj);
                mv[k] = ta ? av : bw; mi[k] = ta ? ai : bj;
                if (ta) ia++; else ib++;
            }
#pragma unroll
            for (int k = 0; k < 16; k++) { sv[t * kTS + k] = mv[k]; si[t * kTS + k] = mi[k]; }
        }
        __syncthreads();
    }
    if (t < kTK) g_knn[row * kTK + t] = si[t];
}

// ---------------- kernel 3/4: gather + norms ----------------
__global__ void gather_kernel(const float* __restrict__ X, IdxArr ia)
{
    int b = blockIdx.x;
    int src = ia.v[b];
    for (int d = threadIdx.x; d < kD; d += blockDim.x)
        g_cent[(size_t)b * kD + d] = X[(size_t)src * kD + d];
}

__global__ void __launch_bounds__(128) cnorm_kernel()
{
    int rc = blockIdx.x;
    float s = 0.f;
    for (int d = threadIdx.x; d < kD; d += 128) {
        float v = g_cent[(size_t)rc * kD + d];
        s = fmaf(v, v, s);
    }
#pragma unroll
    for (int m = 16; m >= 1; m >>= 1) s += __shfl_xor_sync(0xffffffffu, s, m);
    __shared__ float red[4];
    if ((threadIdx.x & 31) == 0) red[threadIdx.x >> 5] = s;
    __syncthreads();
    if (threadIdx.x == 0) g_cnorm[rc] = red[0] + red[1] + red[2] + red[3];
}

// ---------------- kernel 5: assign hi-only -> top-4 candidates (proven) ------
__device__ __forceinline__ bool better(float v, int i, float bv, int bi) {
    return (v < bv) || (v == bv && i < bi);
}

__global__ void __launch_bounds__(256) assign_hi_kernel()
{
    extern __shared__ char smem[];
    __shared__ float cns[kNC];
    __shared__ float sd4[2][128][4];
    __shared__ int   si4[2][128][4];

    const int tid = threadIdx.x;
    const int lane = tid & 31, wid = tid >> 5;
    const int wm = wid & 3, wn = wid >> 2;
    const int gm = lane >> 2, gk = lane & 3;
    const int m0 = blockIdx.x * 128;
    const int r  = blockIdx.y;
    const uint32_t sbase = (uint32_t)__cvta_generic_to_shared(smem);
    const size_t cbase = (size_t)r * kNC * kD;

    if (tid < kNC) cns[tid] = g_cnorm[r * kNC + tid];

    float acc[2][4][4];
#pragma unroll
    for (int mt = 0; mt < 2; mt++)
#pragma unroll
        for (int nt = 0; nt < 4; nt++)
#pragma unroll
            for (int q = 0; q < 4; q++) acc[mt][nt][q] = 0.f;

    auto copy_chunk = [&](int c, int buf) {
        const int koff = c * 32;
        const uint32_t tb = sbase + (uint32_t)buf * kAsgBufB;
#pragma unroll
        for (int q = 0; q < 4; q++) {
            const int idx = q * 256 + tid;
            const int row = idx >> 3, f4 = idx & 7;
            const uint32_t doff = (uint32_t)(row * kPitch + f4 * 4) * 4;
            CP_ASYNC16(tb + doff, g_Bhi + (size_t)(m0 + row) * kD + koff + f4 * 4);
        }
#pragma unroll
        for (int q = 0; q < 2; q++) {
            const int idx = q * 256 + tid;
            const int row = idx >> 3, f4 = idx & 7;
            const uint32_t doff = (uint32_t)(row * kPitch + f4 * 4) * 4;
            CP_ASYNC16(tb + kTileB + doff, g_Chi + cbase + (size_t)row * kD + koff + f4 * 4);
        }
        CP_COMMIT();
    };

    copy_chunk(0, 0);
    copy_chunk(1, 1);

    for (int c = 0; c < kChunks; c++) {
        if (c < kChunks - 1) { CP_WAIT1(); } else { CP_WAIT0(); }
        __syncthreads();
        const int buf = c & 1;
        const float* Ah = reinterpret_cast<const float*>(smem + (size_t)buf * kAsgBufB);
        const float* Bh = reinterpret_cast<const float*>(smem + (size_t)buf * kAsgBufB + kTileB);

#pragma unroll
        for (int kk = 0; kk < 4; kk++) {
            const int kb = kk * 8 + gk;
            uint32_t ah[2][4];
#pragma unroll
            for (int mt = 0; mt < 2; mt++) {
                const int r0 = wm * 32 + mt * 16 + gm;
                ah[mt][0] = __float_as_uint(Ah[r0 * kPitch + kb]);
                ah[mt][1] = __float_as_uint(Ah[(r0 + 8) * kPitch + kb]);
                ah[mt][2] = __float_as_uint(Ah[r0 * kPitch + kb + 4]);
                ah[mt][3] = __float_as_uint(Ah[(r0 + 8) * kPitch + kb + 4]);
            }
#pragma unroll
            for (int nt = 0; nt < 4; nt++) {
                const int rB = wn * 32 + nt * 8 + gm;
                uint32_t bh0 = __float_as_uint(Bh[rB * kPitch + kb]);
                uint32_t bh1 = __float_as_uint(Bh[rB * kPitch + kb + 4]);
                MMA_TF32(acc[0][nt], ah[0], bh0, bh1);
                MMA_TF32(acc[1][nt], ah[1], bh0, bh1);
            }
        }
        __syncthreads();
        if (c + 2 < kChunks) copy_chunk(c + 2, (c + 2) & 1);
    }

    // top-4 candidates per point
#pragma unroll
    for (int mt = 0; mt < 2; mt++) {
#pragma unroll
        for (int half = 0; half < 2; half++) {
            float tv[4]; int ti[4];
#pragma unroll
            for (int q = 0; q < 4; q++) { tv[q] = 3.402823466e38f; ti[q] = 0x7fffffff; }
#pragma unroll
            for (int nt = 0; nt < 4; nt++) {
                const int c0 = wn * 32 + nt * 8 + 2 * gk;
#pragma unroll
                for (int hh = 0; hh < 2; hh++) {
                    float v = cns[c0 + hh] - 2.f * acc[mt][nt][half * 2 + hh];
                    int   i = c0 + hh;
                    if (better(v, i, tv[3], ti[3])) {
                        float cvv = v; int cii = i;
#pragma unroll
                        for (int q = 0; q < 4; q++) {
                            if (better(cvv, cii, tv[q], ti[q])) {
                                float fv = tv[q]; int fi = ti[q];
                                tv[q] = cvv; ti[q] = cii; cvv = fv; cii = fi;
                            }
                        }
                    }
                }
            }
#pragma unroll
            for (int m = 1; m < 4; m <<= 1) {
                float ov[4]; int oi[4];
#pragma unroll
                for (int q = 0; q < 4; q++) {
                    ov[q] = __shfl_xor_sync(0xffffffffu, tv[q], m);
                    oi[q] = __shfl_xor_sync(0xffffffffu, ti[q], m);
                }
                float mv[4]; int mi[4];
                int ia = 0, ib = 0;
#pragma unroll
                for (int q = 0; q < 4; q++) {
                    bool ta = better(tv[ia], ti[ia], ov[ib], oi[ib]);
                    mv[q] = ta ? tv[ia] : ov[ib];
                    mi[q] = ta ? ti[ia] : oi[ib];
                    if (ta) ia++; else ib++;
                }
#pragma unroll
                for (int q = 0; q < 4; q++) { tv[q] = mv[q]; ti[q] = mi[q]; }
            }
            if (gk == 0) {
                const int rl = wm * 32 + mt * 16 + half * 8 + gm;
#pragma unroll
                for (int q = 0; q < 4; q++) { sd4[wn][rl][q] = tv[q]; si4[wn][rl][q] = ti[q]; }
            }
        }
    }
    __syncthreads();
    if (tid < 128) {
        float mv[4]; int mi[4];
        int ia = 0, ib = 0;
#pragma unroll
        for (int q = 0; q < 4; q++) {
            bool ta = better(sd4[0][tid][ia], si4[0][tid][ia], sd4[1][tid][ib], si4[1][tid][ib]);
            mv[q] = ta ? sd4[0][tid][ia] : sd4[1][tid][ib];
            mi[q] = ta ? si4[0][tid][ia] : si4[1][tid][ib];
            if (ta) ia++; else ib++;
        }
        (void)mv;
        g_cand4[r * kN + m0 + tid] = make_int4(mi[0], mi[1], mi[2], mi[3]);
    }
}

// ---------------- kernel 5b: exact fp32 refine (all runs per launch) ---------
__global__ void __launch_bounds__(256) refine_kernel(const float* __restrict__ X)
{
    const int wid = threadIdx.x >> 5, lane = threadIdx.x & 31;
    const int p = blockIdx.x * 8 + wid;

    float x[16];
#pragma unroll
    for (int u = 0; u < 16; u++) x[u] = X[(size_t)p * kD + u * 32 + lane];

#pragma unroll
    for (int r = 0; r < kNR; r++) {
        const int4 cd = g_cand4[r * kN + p];
        const int cands[4] = {cd.x, cd.y, cd.z, cd.w};
        const float* C = g_cent + (size_t)r * kNC * kD;
        float bv = 3.402823466e38f; int bi = 0x7fffffff;
#pragma unroll
        for (int q = 0; q < 4; q++) {
            const int c = cands[q];
            float s = 0.f;
#pragma unroll
            for (int u = 0; u < 16; u++) s = fmaf(x[u], C[(size_t)c * kD + u * 32 + lane], s);
#pragma unroll
            for (int m = 16; m >= 1; m >>= 1) s += __shfl_xor_sync(0xffffffffu, s, m);
            float v = g_cnorm[r * kNC + c] - 2.f * s;
            if (better(v, c, bv, bi)) { bv = v; bi = c; }
        }
        if (lane == 0) g_labels[r * kN + p] = bi;
    }
}

// ---------------- kernel 6a: point-centric partial sums (d-split) ------------
__global__ void __launch_bounds__(256) partial_kernel(const float* __restrict__ X)
{
    extern __shared__ float sm[];
    float* ssum = sm;                            // [kNC][256]
    int*   slab = (int*)(sm + kNC * 256);        // [kCHP]
    int*   scnt = (int*)(sm + kNC * 256) + kCHP; // [kNC]

    const int ch = blockIdx.x;
    const int r  = blockIdx.y >> 1, dh = blockIdx.y & 1;
    const int t = threadIdx.x;
    const int d = dh * 256 + t;
    const int p0 = ch * kCHP;
    const int* lab = g_labels + r * kN;

#pragma unroll
    for (int c = 0; c < kNC; c++) ssum[c * 256 + t] = 0.f;
    if (t < kNC) scnt[t] = 0;
    slab[t] = lab[p0 + t];
    __syncthreads();
    if (dh == 0) atomicAdd(&scnt[slab[t]], 1);
    __syncthreads();

    for (int i = 0; i < kCHP; i += 8) {
        float x0 = X[(size_t)(p0 + i + 0) * kD + d];
        float x1 = X[(size_t)(p0 + i + 1) * kD + d];
        float x2 = X[(size_t)(p0 + i + 2) * kD + d];
        float x3 = X[(size_t)(p0 + i + 3) * kD + d];
        float x4 = X[(size_t)(p0 + i + 4) * kD + d];
        float x5 = X[(size_t)(p0 + i + 5) * kD + d];
        float x6 = X[(size_t)(p0 + i + 6) * kD + d];
        float x7 = X[(size_t)(p0 + i + 7) * kD + d];
        int c0 = slab[i + 0], c1 = slab[i + 1], c2 = slab[i + 2], c3 = slab[i + 3];
        int c4 = slab[i + 4], c5 = slab[i + 5], c6 = slab[i + 6], c7 = slab[i + 7];
        ssum[c0 * 256 + t] += x0;
        ssum[c1 * 256 + t] += x1;
        ssum[c2 * 256 + t] += x2;
        ssum[c3 * 256 + t] += x3;
        ssum[c4 * 256 + t] += x4;
        ssum[c5 * 256 + t] += x5;
        ssum[c6 * 256 + t] += x6;
        ssum[c7 * 256 + t] += x7;
    }
    __syncthreads();

    const size_t base = (size_t)(r * kCH + ch) * kNC;
#pragma unroll
    for (int c = 0; c < kNC; c++)
        g_part[(base + c) * kD + d] = ssum[c * 256 + t];
    if (dh == 0 && t < kNC) g_pcnt[base + t] = scnt[t];
}

// ---------------- kernel 6b: combine partials -> centroid + norm -------------
__global__ void __launch_bounds__(512) combine_kernel()
{
    __shared__ float fred[16];
    const int c = blockIdx.x, r = blockIdx.y;
    const int t = threadIdx.x;
    const unsigned lane = t & 31;

    int cnt = 0;
    float sum = 0.f;
#pragma unroll
    for (int ch = 0; ch < kCH; ch++) {
        size_t base = (size_t)(r * kCH + ch) * kNC + c;
        cnt += g_pcnt[base];
        sum += g_part[base * kD + t];
    }
    const int rc = r * kNC + c;
    float oldc = g_cent[(size_t)rc * kD + t];
    float newc = (cnt > 0) ? (sum / (float)cnt) : oldc;
    g_cent[(size_t)rc * kD + t] = newc;

    float sq = newc * newc;
#pragma unroll
    for (int m = 16; m >= 1; m >>= 1) sq += __shfl_xor_sync(0xffffffffu, sq, m);
    if (lane == 0) fred[t >> 5] = sq;
    __syncthreads();
    if (t == 0) {
        float s = 0.f;
        for (int w = 0; w < 16; w++) s += fred[w];
        g_cnorm[rc] = s;
    }
}

// ---------------- kernel 7: scatter final output ----------------
__global__ void __launch_bounds__(256) scatter_kernel(
    const float* __restrict__ adj, float* __restrict__ out)
{
    int e = blockIdx.x * blockDim.x + threadIdx.x;
    int i = e >> 4;
    int j = g_knn[e];
    float v = adj[(size_t)i * kN + j];
    bool m = false;
#pragma unroll
    for (int r = 0; r < kNR; r++)
        m |= (g_labels[r * kN + i] == g_labels[r * kN + j]);
    out[(size_t)i * kN + j] = v + (m ? 1.f : 0.f);
}

// ---------------- launcher ----------------
extern "C" void kernel_launch(void* const* d_in, const int* in_sizes, int n_in,
                              void* d_out, int out_size)
{
    (void)in_sizes; (void)n_in; (void)out_size;
    const float* adj     = (const float*)d_in[0];
    const float* student = (const float*)d_in[1];
    const float* teacher = (const float*)d_in[2];
    float* out = (float*)d_out;

    constexpr size_t kPartSmem = (size_t)kNC * 256 * 4 + kCHP * 4 + kNC * 4;
    constexpr size_t kGemmSmem = 8 * (size_t)kTileB;      // 144 KB (3x gemm)
    constexpr size_t kAsgSmem  = 2 * (size_t)kAsgBufB;    // 55.3 KB
    static cudaStream_t s2 = nullptr, s1 = nullptr;
    static cudaEvent_t ev_fork = nullptr, ev_join = nullptr, ev_main = nullptr, ev_split = nullptr;
    if (!s2) {
        int lo, hi;
        cudaDeviceGetStreamPriorityRange(&lo, &hi);
        cudaStreamCreateWithPriority(&s2, cudaStreamNonBlocking, hi);
        cudaStreamCreateWithPriority(&s1, cudaStreamNonBlocking, lo);
        cudaEventCreateWithFlags(&ev_fork, cudaEventDisableTiming);
        cudaEventCreateWithFlags(&ev_join, cudaEventDisableTiming);
        cudaEventCreateWithFlags(&ev_main, cudaEventDisableTiming);
        cudaEventCreateWithFlags(&ev_split, cudaEventDisableTiming);
        cudaFuncSetAttribute(partial_kernel,
                             cudaFuncAttributeMaxDynamicSharedMemorySize, (int)kPartSmem);
        cudaFuncSetAttribute(gemm_mma_kernel,
                             cudaFuncAttributeMaxDynamicSharedMemorySize, (int)kGemmSmem);
        cudaFuncSetAttribute(assign_hi_kernel,
                             cudaFuncAttributeMaxDynamicSharedMemorySize, (int)kAsgSmem);
    }

    IdxArr ia;
    compute_init_indices(ia.v);

    cudaEventRecord(ev_fork, 0);
    cudaStreamWaitEvent(s2, ev_fork, 0);
    cudaStreamWaitEvent(s1, ev_fork, 0);

    // s1: tf32 hi/lo split (Bhi also feeds assign on s2)
    split_kernel<<<(kN * kD) / (256 * 4), 256, 0, s1>>>(student, teacher);
    cudaEventRecord(ev_split, s1);

    // s2: serial kmeans chain (hi tensor candidates + exact fp32 refine)
    gather_kernel<<<kRC, 128, 0, s2>>>(teacher, ia);
    cnorm_kernel<<<kRC, 128, 0, s2>>>();
    split_cent_hi_kernel<<<(kRC * kD) / (256 * 4), 256, 0, s2>>>();
    cudaStreamWaitEvent(s2, ev_split, 0);
    dim3 ga(kN / 128, kNR), gp(kCH, kNR * 2), gc(kNC, kNR);
    for (int it = 0; it < kIters; it++) {
        assign_hi_kernel<<<ga, 256, kAsgSmem, s2>>>();
        refine_kernel<<<kN / 8, 256, 0, s2>>>(teacher);
        partial_kernel<<<gp, 256, kPartSmem, s2>>>(teacher);
        combine_kernel<<<gc, 512, 0, s2>>>();
        split_cent_hi_kernel<<<(kRC * kD) / (256 * 4), 256, 0, s2>>>();
    }
    assign_hi_kernel<<<ga, 256, kAsgSmem, s2>>>();
    refine_kernel<<<kN / 8, 256, 0, s2>>>(teacher);
    cudaEventRecord(ev_join, s2);

    // s1: 3xTF32 sim GEMM -> direct top-16 -> zero out
    dim3 g1(kN / 128, kN / 128);
    gemm_mma_kernel<<<g1, 256, kGemmSmem, s1>>>(out);
    topk_kernel<<<kN, 256, 0, s1>>>(out);
    cudaMemsetAsync(d_out, 0, (size_t)kN * kN * sizeof(float), s1);
    cudaEventRecord(ev_main, s1);

    cudaStreamWaitEvent(0, ev_join, 0);
    cudaStreamWaitEvent(0, ev_main, 0);
    scatter_kernel<<<kN * kTK / 256, 256>>>(adj, out);
}

// round 16
// speedup vs baseline: 1.9001x; 1.1225x over previous
#include <cuda_runtime.h>
#include <cstdint>
#include <cstring>
#include <vector>
#include <algorithm>

namespace {
constexpr int kN = 8192, kD = 512, kNC = 64, kNR = 5, kRC = kNC * kNR;
constexpr int kTK = 16, kIters = 20;
constexpr int kCH = 32, kCHP = kN / kCH;   // 32 chunks x 256 points
constexpr int kCand = 32;                  // topk candidate count

// ---------------- host-side JAX threefry2x32 ----------------
struct U2 { uint32_t a, b; };
static inline uint32_t rotl32(uint32_t v, int r) { return (v << r) | (v >> (32 - r)); }

static U2 threefry(U2 key, uint32_t x0, uint32_t x1) {
    uint32_t ks0 = key.a, ks1 = key.b, ks2 = key.a ^ key.b ^ 0x1BD11BDAu;
    const int ra[4] = {13, 15, 26, 6}, rb[4] = {17, 29, 16, 24};
    x0 += ks0; x1 += ks1;
    for (int i = 0; i < 4; i++) { x0 += x1; x1 = rotl32(x1, ra[i]); x1 ^= x0; }
    x0 += ks1; x1 += ks2 + 1u;
    for (int i = 0; i < 4; i++) { x0 += x1; x1 = rotl32(x1, rb[i]); x1 ^= x0; }
    x0 += ks2; x1 += ks0 + 2u;
    for (int i = 0; i < 4; i++) { x0 += x1; x1 = rotl32(x1, ra[i]); x1 ^= x0; }
    x0 += ks0; x1 += ks1 + 3u;
    for (int i = 0; i < 4; i++) { x0 += x1; x1 = rotl32(x1, rb[i]); x1 ^= x0; }
    x0 += ks1; x1 += ks2 + 4u;
    for (int i = 0; i < 4; i++) { x0 += x1; x1 = rotl32(x1, ra[i]); x1 ^= x0; }
    x0 += ks2; x1 += ks0 + 5u;
    return {x0, x1};
}

constexpr bool kPartitionable = true;

static void split_keys(U2 key, int n, U2* out) {
    if (kPartitionable) {
        for (int i = 0; i < n; i++) out[i] = threefry(key, 0u, (uint32_t)i);
    } else {
        std::vector<uint32_t> o(2 * n);
        for (int i = 0; i < n; i++) {
            U2 y = threefry(key, (uint32_t)i, (uint32_t)(n + i));
            o[i] = y.a; o[n + i] = y.b;
        }
        for (int j = 0; j < n; j++) out[j] = { o[2 * j], o[2 * j + 1] };
    }
}

static void random_bits32(U2 key, int n, uint32_t* bits) {
    if (kPartitionable) {
        for (int i = 0; i < n; i++) {
            U2 y = threefry(key, 0u, (uint32_t)i);
            bits[i] = y.a ^ y.b;
        }
    } else {
        int h = n / 2;
        for (int i = 0; i < h; i++) {
            U2 y = threefry(key, (uint32_t)i, (uint32_t)(h + i));
            bits[i] = y.a; bits[h + i] = y.b;
        }
    }
}

static void compute_init_indices(int out_idx[kRC]) {
    U2 master{0u, 1234u};
    U2 runkeys[kNR];
    split_keys(master, kNR, runkeys);
    std::vector<int> val(kN), tmp(kN);
    std::vector<uint64_t> kv(kN);
    std::vector<uint32_t> bits(kN);
    for (int r = 0; r < kNR; r++) {
        for (int i = 0; i < kN; i++) val[i] = i;
        U2 cur = runkeys[r];
        for (int round = 0; round < 2; round++) {
            U2 nk[2];
            split_keys(cur, 2, nk);
            cur = nk[0];
            random_bits32(nk[1], kN, bits.data());
            for (int i = 0; i < kN; i++)
                kv[i] = ((uint64_t)bits[i] << 32) | (uint32_t)i;
            std::sort(kv.begin(), kv.end());
            for (int i = 0; i < kN; i++) tmp[i] = val[(uint32_t)(kv[i] & 0xffffffffu)];
            val.swap(tmp);
        }
        for (int c = 0; c < kNC; c++) out_idx[r * kNC + c] = val[c];
    }
}
} // namespace

// ---------------- device scratch ----------------
__device__ float g_cent[kRC * kD];
__device__ float g_cnorm[kRC];
__device__ int   g_labels[kNR * kN];
__device__ int4  g_cand4[kNR * kN];
__device__ int   g_knn[kN * kTK];
__device__ int   g_cand[kN * kCand];
__device__ float g_part[(size_t)kNR * kCH * kNC * kD];
__device__ int   g_pcnt[kNR * kCH * kNC];
__device__ float g_Ahi[(size_t)kN * kD];   // student hi (tf32)
__device__ float g_Bhi[(size_t)kN * kD];   // teacher hi (tf32)
__device__ float g_Chi[(size_t)kRC * kD];  // centroid hi (tf32)

struct IdxArr { int v[kRC]; };

// ---------------- tf32 helpers ----------------
__device__ __forceinline__ float tf32r(float x) {
    uint32_t u; asm("cvt.rna.tf32.f32 %0,%1;" : "=r"(u) : "f"(x));
    return __uint_as_float(u);
}

#define MMA_TF32(d, a, b0, b1) \
    asm volatile( \
        "mma.sync.aligned.m16n8k8.row.col.f32.tf32.tf32.f32 " \
        "{%0,%1,%2,%3}, {%4,%5,%6,%7}, {%8,%9}, {%0,%1,%2,%3};" \
        : "+f"((d)[0]), "+f"((d)[1]), "+f"((d)[2]), "+f"((d)[3]) \
        : "r"((a)[0]), "r"((a)[1]), "r"((a)[2]), "r"((a)[3]), \
          "r"(b0), "r"(b1))

#define CP_ASYNC16(dst, src) \
    asm volatile("cp.async.cg.shared.global [%0], [%1], 16;" :: "r"(dst), "l"(src) : "memory")
#define CP_COMMIT() asm volatile("cp.async.commit_group;" ::: "memory")
#define CP_WAIT1()  asm volatile("cp.async.wait_group 1;" ::: "memory")
#define CP_WAIT0()  asm volatile("cp.async.wait_group 0;" ::: "memory")

namespace {
constexpr int kPitch = 36;
constexpr int kATileB = 128 * kPitch * 4;   // 18432
constexpr int kBTileB = 64 * kPitch * 4;    // 9216
constexpr int kChunks = kD / 32;            // 16
constexpr int kGemmBufB = 2 * kATileB;      // Ahi + Bhi
constexpr int kAsgBufB  = kATileB + kBTileB;
}

// ---------------- kernel 0: fp32 -> tf32 hi (inputs) ----------------
__global__ void __launch_bounds__(256) split_hi_kernel(const float* __restrict__ A,
                                                       const float* __restrict__ B)
{
    size_t i = ((size_t)blockIdx.x * 256 + threadIdx.x) * 4;
    float4 a = *reinterpret_cast<const float4*>(A + i);
    float4 b = *reinterpret_cast<const float4*>(B + i);
    float4 ah, bh;
    ah.x = tf32r(a.x); ah.y = tf32r(a.y); ah.z = tf32r(a.z); ah.w = tf32r(a.w);
    bh.x = tf32r(b.x); bh.y = tf32r(b.y); bh.z = tf32r(b.z); bh.w = tf32r(b.w);
    *reinterpret_cast<float4*>(g_Ahi + i) = ah;
    *reinterpret_cast<float4*>(g_Bhi + i) = bh;
}

__global__ void __launch_bounds__(256) split_cent_hi_kernel()
{
    size_t i = ((size_t)blockIdx.x * 256 + threadIdx.x) * 4;
    float4 c = *reinterpret_cast<const float4*>(g_cent + i);
    float4 ch;
    ch.x = tf32r(c.x); ch.y = tf32r(c.y); ch.z = tf32r(c.z); ch.w = tf32r(c.w);
    *reinterpret_cast<float4*>(g_Chi + i) = ch;
}

// ---------------- kernel 1: sim GEMM, hi-only tf32 (proven R12-14) -----------
__global__ void __launch_bounds__(256) gemm_hi_kernel(float* __restrict__ C)
{
    extern __shared__ char smem[];
    const int tid = threadIdx.x;
    const int lane = tid & 31, wid = tid >> 5;
    const int wm = wid & 3, wn = wid >> 2;
    const int gm = lane >> 2, gk = lane & 3;
    const int n0 = blockIdx.x * 128, m0 = blockIdx.y * 128;
    const uint32_t sbase = (uint32_t)__cvta_generic_to_shared(smem);

    float acc[2][8][4];
#pragma unroll
    for (int mt = 0; mt < 2; mt++)
#pragma unroll
        for (int nt = 0; nt < 8; nt++)
#pragma unroll
            for (int q = 0; q < 4; q++) acc[mt][nt][q] = 0.f;

    auto copy_chunk = [&](int c, int buf) {
        const int koff = c * 32;
        const uint32_t tb = sbase + (uint32_t)buf * kGemmBufB;
#pragma unroll
        for (int q = 0; q < 4; q++) {
            const int idx = q * 256 + tid;
            const int row = idx >> 3, f4 = idx & 7;
            const uint32_t doff = (uint32_t)(row * kPitch + f4 * 4) * 4;
            CP_ASYNC16(tb + doff, g_Ahi + (size_t)(m0 + row) * kD + koff + f4 * 4);
            CP_ASYNC16(tb + kATileB + doff, g_Bhi + (size_t)(n0 + row) * kD + koff + f4 * 4);
        }
        CP_COMMIT();
    };

    copy_chunk(0, 0);
    copy_chunk(1, 1);

    for (int c = 0; c < kChunks; c++) {
        if (c < kChunks - 1) { CP_WAIT1(); } else { CP_WAIT0(); }
        __syncthreads();
        const int buf = c & 1;
        const float* Ah = reinterpret_cast<const float*>(smem + (size_t)buf * kGemmBufB);
        const float* Bh = reinterpret_cast<const float*>(smem + (size_t)buf * kGemmBufB + kATileB);

#pragma unroll
        for (int kk = 0; kk < 4; kk++) {
            const int kb = kk * 8 + gk;
            uint32_t ah[2][4];
#pragma unroll
            for (int mt = 0; mt < 2; mt++) {
                const int r0 = wm * 32 + mt * 16 + gm;
                ah[mt][0] = __float_as_uint(Ah[r0 * kPitch + kb]);
                ah[mt][1] = __float_as_uint(Ah[(r0 + 8) * kPitch + kb]);
                ah[mt][2] = __float_as_uint(Ah[r0 * kPitch + kb + 4]);
                ah[mt][3] = __float_as_uint(Ah[(r0 + 8) * kPitch + kb + 4]);
            }
#pragma unroll
            for (int nt = 0; nt < 8; nt++) {
                const int rB = wn * 64 + nt * 8 + gm;
                uint32_t bh0 = __float_as_uint(Bh[rB * kPitch + kb]);
                uint32_t bh1 = __float_as_uint(Bh[rB * kPitch + kb + 4]);
                MMA_TF32(acc[0][nt], ah[0], bh0, bh1);
                MMA_TF32(acc[1][nt], ah[1], bh0, bh1);
            }
        }
        __syncthreads();
        if (c + 2 < kChunks) copy_chunk(c + 2, (c + 2) & 1);
    }

#pragma unroll
    for (int mt = 0; mt < 2; mt++) {
#pragma unroll
        for (int nt = 0; nt < 8; nt++) {
            const int r0 = m0 + wm * 32 + mt * 16 + gm;
            const int r1 = r0 + 8;
            const int col = n0 + wn * 64 + nt * 8 + 2 * gk;
            float2 v0, v1;
            v0.x = acc[mt][nt][0] + ((r0 == col) ? 10.f : 0.f);
            v0.y = acc[mt][nt][1] + ((r0 == col + 1) ? 10.f : 0.f);
            v1.x = acc[mt][nt][2] + ((r1 == col) ? 10.f : 0.f);
            v1.y = acc[mt][nt][3] + ((r1 == col + 1) ? 10.f : 0.f);
            *reinterpret_cast<float2*>(&C[(size_t)r0 * kN + col]) = v0;
            *reinterpret_cast<float2*>(&C[(size_t)r1 * kN + col]) = v1;
        }
    }
}

// ---------------- kernel 2: top-32 v2 (per-thread top-8 + smem merges) -------
__device__ __forceinline__ bool beats(float v1, int i1, float v2, int i2) {
    return (v1 > v2) || (v1 == v2 && i1 < i2);
}

__global__ void __launch_bounds__(256) topk32_kernel(const float* __restrict__ sim)
{
    __shared__ float av[2048];
    __shared__ int   ai[2048];
    __shared__ float bv[2048];
    __shared__ int   bi[2048];
    const int row = blockIdx.x, t = threadIdx.x;

    // phase 1: per-thread top-8 over strided segment (no spills: 8+8 regs)
    float tv[8]; int ti[8];
#pragma unroll
    for (int k = 0; k < 8; k++) { tv[k] = -3.402823466e38f; ti[k] = 0x7fffffff; }
    const float* rp = sim + (size_t)row * kN;
    for (int j = t; j < kN; j += 256) {
        float v = rp[j];
        if (beats(v, j, tv[7], ti[7])) {
            float cv = v; int ci = j;
#pragma unroll
            for (int k = 0; k < 8; k++) {
                if (beats(cv, ci, tv[k], ti[k])) {
                    float fv = tv[k]; int fi = ti[k];
                    tv[k] = cv; ti[k] = ci; cv = fv; ci = fi;
                }
            }
        }
    }
#pragma unroll
    for (int k = 0; k < 8; k++) { av[t * 8 + k] = tv[k]; ai[t * 8 + k] = ti[k]; }
    __syncthreads();

    // smem two-pointer merge helper (no register lists)
    auto merge = [&](const float* sV, const int* sI, float* dV, int* dI,
                     int o0, int l0, int o1, int l1, int od, int lo) {
        int ia = 0, ib = 0;
        for (int k = 0; k < lo; k++) {
            bool ta;
            if (ia < l0 && ib < l1)
                ta = beats(sV[o0 + ia], sI[o0 + ia], sV[o1 + ib], sI[o1 + ib]);
            else
                ta = (ia < l0);
            if (ta) { dV[od + k] = sV[o0 + ia]; dI[od + k] = sI[o0 + ia]; ia++; }
            else    { dV[od + k] = sV[o1 + ib]; dI[od + k] = sI[o1 + ib]; ib++; }
        }
    };

    // L1: 256 lists(8) -> 128 lists(16)  A->B
    if (t < 128) merge(av, ai, bv, bi, t * 16, 8, t * 16 + 8, 8, t * 16, 16);
    __syncthreads();
    // L2: 128 lists(16) -> 64 lists(32)  B->A
    if (t < 64) merge(bv, bi, av, ai, t * 32, 16, t * 32 + 16, 16, t * 32, 32);
    __syncthreads();
    // L3..L8: capped-32 merges, ping-pong
    int nlists = 64;
    bool inA = true;
    while (nlists > 1) {
        int half = nlists >> 1;
        if (t < half) {
            if (inA) merge(av, ai, bv, bi, (2 * t) * 32, 32, (2 * t + 1) * 32, 32, t * 32, 32);
            else     merge(bv, bi, av, ai, (2 * t) * 32, 32, (2 * t + 1) * 32, 32, t * 32, 32);
        }
        __syncthreads();
        inA = !inA;
        nlists = half;
    }
    if (t < kCand) g_cand[row * kCand + t] = inA ? ai[t] : bi[t];
}

// ---------------- kernel 2b: fp32 rescore -> exact top-16 (proven) -----------
__global__ void __launch_bounds__(256) rescore_kernel(const float* __restrict__ S,
                                                      const float* __restrict__ T)
{
    __shared__ float cv[kCand];
    __shared__ int   ci[kCand];
    const int row = blockIdx.x;
    const int tid = threadIdx.x;
    const int wid = tid >> 5, lane = tid & 31;

#pragma unroll
    for (int k = 0; k < 4; k++) {
        const int slot = wid + 8 * k;
        const int cand = g_cand[row * kCand + slot];
        float s = 0.f;
#pragma unroll
        for (int u = 0; u < 16; u++)
            s = fmaf(S[(size_t)row * kD + u * 32 + lane],
                     T[(size_t)cand * kD + u * 32 + lane], s);
#pragma unroll
        for (int m = 16; m >= 1; m >>= 1) s += __shfl_xor_sync(0xffffffffu, s, m);
        if (lane == 0) {
            if (cand == row) s += 10.f;
            cv[slot] = s; ci[slot] = cand;
        }
    }
    __syncthreads();
    if (tid == 0) {
        unsigned used = 0;
        for (int k = 0; k < kTK; k++) {
            float bvv = -3.402823466e38f; int bii = 0x7fffffff, bs = -1;
            for (int q = 0; q < kCand; q++) {
                if (used & (1u << q)) continue;
                if (beats(cv[q], ci[q], bvv, bii)) { bvv = cv[q]; bii = ci[q]; bs = q; }
            }
            used |= (1u << bs);
            g_knn[row * kTK + k] = bii;
        }
    }
}

// ---------------- kernel 3/4: gather + norms ----------------
__global__ void gather_kernel(const float* __restrict__ X, IdxArr ia)
{
    int b = blockIdx.x;
    int src = ia.v[b];
    for (int d = threadIdx.x; d < kD; d += blockDim.x)
        g_cent[(size_t)b * kD + d] = X[(size_t)src * kD + d];
}

__global__ void __launch_bounds__(128) cnorm_kernel()
{
    int rc = blockIdx.x;
    float s = 0.f;
    for (int d = threadIdx.x; d < kD; d += 128) {
        float v = g_cent[(size_t)rc * kD + d];
        s = fmaf(v, v, s);
    }
#pragma unroll
    for (int m = 16; m >= 1; m >>= 1) s += __shfl_xor_sync(0xffffffffu, s, m);
    __shared__ float red[4];
    if ((threadIdx.x & 31) == 0) red[threadIdx.x >> 5] = s;
    __syncthreads();
    if (threadIdx.x == 0) g_cnorm[rc] = red[0] + red[1] + red[2] + red[3];
}

// ---------------- kernel 5: assign hi-only -> top-4 candidates (proven) ------
__device__ __forceinline__ bool better(float v, int i, float bv, int bi) {
    return (v < bv) || (v == bv && i < bi);
}

__global__ void __launch_bounds__(256) assign_hi_kernel()
{
    extern __shared__ char smem[];
    __shared__ float cns[kNC];
    __shared__ float sd4[2][128][4];
    __shared__ int   si4[2][128][4];

    const int tid = threadIdx.x;
    const int lane = tid & 31, wid = tid >> 5;
    const int wm = wid & 3, wn = wid >> 2;
    const int gm = lane >> 2, gk = lane & 3;
    const int m0 = blockIdx.x * 128;
    const int r  = blockIdx.y;
    const uint32_t sbase = (uint32_t)__cvta_generic_to_shared(smem);
    const size_t cbase = (size_t)r * kNC * kD;

    if (tid < kNC) cns[tid] = g_cnorm[r * kNC + tid];

    float acc[2][4][4];
#pragma unroll
    for (int mt = 0; mt < 2; mt++)
#pragma unroll
        for (int nt = 0; nt < 4; nt++)
#pragma unroll
            for (int q = 0; q < 4; q++) acc[mt][nt][q] = 0.f;

    auto copy_chunk = [&](int c, int buf) {
        const int koff = c * 32;
        const uint32_t tb = sbase + (uint32_t)buf * kAsgBufB;
#pragma unroll
        for (int q = 0; q < 4; q++) {
            const int idx = q * 256 + tid;
            const int row = idx >> 3, f4 = idx & 7;
            const uint32_t doff = (uint32_t)(row * kPitch + f4 * 4) * 4;
            CP_ASYNC16(tb + doff, g_Bhi + (size_t)(m0 + row) * kD + koff + f4 * 4);
        }
#pragma unroll
        for (int q = 0; q < 2; q++) {
            const int idx = q * 256 + tid;
            const int row = idx >> 3, f4 = idx & 7;
            const uint32_t doff = (uint32_t)(row * kPitch + f4 * 4) * 4;
            CP_ASYNC16(tb + kATileB + doff, g_Chi + cbase + (size_t)row * kD + koff + f4 * 4);
        }
        CP_COMMIT();
    };

    copy_chunk(0, 0);
    copy_chunk(1, 1);

    for (int c = 0; c < kChunks; c++) {
        if (c < kChunks - 1) { CP_WAIT1(); } else { CP_WAIT0(); }
        __syncthreads();
        const int buf = c & 1;
        const float* Ah = reinterpret_cast<const float*>(smem + (size_t)buf * kAsgBufB);
        const float* Bh = reinterpret_cast<const float*>(smem + (size_t)buf * kAsgBufB + kATileB);

#pragma unroll
        for (int kk = 0; kk < 4; kk++) {
            const int kb = kk * 8 + gk;
            uint32_t ah[2][4];
#pragma unroll
            for (int mt = 0; mt < 2; mt++) {
                const int r0 = wm * 32 + mt * 16 + gm;
                ah[mt][0] = __float_as_uint(Ah[r0 * kPitch + kb]);
                ah[mt][1] = __float_as_uint(Ah[(r0 + 8) * kPitch + kb]);
                ah[mt][2] = __float_as_uint(Ah[r0 * kPitch + kb + 4]);
                ah[mt][3] = __float_as_uint(Ah[(r0 + 8) * kPitch + kb + 4]);
            }
#pragma unroll
            for (int nt = 0; nt < 4; nt++) {
                const int rB = wn * 32 + nt * 8 + gm;
                uint32_t bh0 = __float_as_uint(Bh[rB * kPitch + kb]);
                uint32_t bh1 = __float_as_uint(Bh[rB * kPitch + kb + 4]);
                MMA_TF32(acc[0][nt], ah[0], bh0, bh1);
                MMA_TF32(acc[1][nt], ah[1], bh0, bh1);
            }
        }
        __syncthreads();
        if (c + 2 < kChunks) copy_chunk(c + 2, (c + 2) & 1);
    }

#pragma unroll
    for (int mt = 0; mt < 2; mt++) {
#pragma unroll
        for (int half = 0; half < 2; half++) {
            float tv[4]; int ti[4];
#pragma unroll
            for (int q = 0; q < 4; q++) { tv[q] = 3.402823466e38f; ti[q] = 0x7fffffff; }
#pragma unroll
            for (int nt = 0; nt < 4; nt++) {
                const int c0 = wn * 32 + nt * 8 + 2 * gk;
#pragma unroll
                for (int hh = 0; hh < 2; hh++) {
                    float v = cns[c0 + hh] - 2.f * acc[mt][nt][half * 2 + hh];
                    int   i = c0 + hh;
                    if (better(v, i, tv[3], ti[3])) {
                        float cvv = v; int cii = i;
#pragma unroll
                        for (int q = 0; q < 4; q++) {
                            if (better(cvv, cii, tv[q], ti[q])) {
                                float fv = tv[q]; int fi = ti[q];
                                tv[q] = cvv; ti[q] = cii; cvv = fv; cii = fi;
                            }
                        }
                    }
                }
            }
#pragma unroll
            for (int m = 1; m < 4; m <<= 1) {
                float ov[4]; int oi[4];
#pragma unroll
                for (int q = 0; q < 4; q++) {
                    ov[q] = __shfl_xor_sync(0xffffffffu, tv[q], m);
                    oi[q] = __shfl_xor_sync(0xffffffffu, ti[q], m);
                }
                float mv[4]; int mi[4];
                int ia2 = 0, ib2 = 0;
#pragma unroll
                for (int q = 0; q < 4; q++) {
                    bool ta = better(tv[ia2], ti[ia2], ov[ib2], oi[ib2]);
                    mv[q] = ta ? tv[ia2] : ov[ib2];
                    mi[q] = ta ? ti[ia2] : oi[ib2];
                    if (ta) ia2++; else ib2++;
                }
#pragma unroll
                for (int q = 0; q < 4; q++) { tv[q] = mv[q]; ti[q] = mi[q]; }
            }
            if (gk == 0) {
                const int rl = wm * 32 + mt * 16 + half * 8 + gm;
#pragma unroll
                for (int q = 0; q < 4; q++) { sd4[wn][rl][q] = tv[q]; si4[wn][rl][q] = ti[q]; }
            }
        }
    }
    __syncthreads();
    if (tid < 128) {
        float mv[4]; int mi[4];
        int ia2 = 0, ib2 = 0;
#pragma unroll
        for (int q = 0; q < 4; q++) {
            bool ta = better(sd4[0][tid][ia2], si4[0][tid][ia2], sd4[1][tid][ib2], si4[1][tid][ib2]);
            mv[q] = ta ? sd4[0][tid][ia2] : sd4[1][tid][ib2];
            mi[q] = ta ? si4[0][tid][ia2] : si4[1][tid][ib2];
            if (ta) ia2++; else ib2++;
        }
        (void)mv;
        g_cand4[r * kN + m0 + tid] = make_int4(mi[0], mi[1], mi[2], mi[3]);
    }
}

// ---------------- kernel 5b: exact fp32 refine (all runs per launch) ---------
__global__ void __launch_bounds__(256) refine_kernel(const float* __restrict__ X)
{
    const int wid = threadIdx.x >> 5, lane = threadIdx.x & 31;
    const int p = blockIdx.x * 8 + wid;

    float x[16];
#pragma unroll
    for (int u = 0; u < 16; u++) x[u] = X[(size_t)p * kD + u * 32 + lane];

#pragma unroll
    for (int r = 0; r < kNR; r++) {
        const int4 cd = g_cand4[r * kN + p];
        const int cands[4] = {cd.x, cd.y, cd.z, cd.w};
        const float* C = g_cent + (size_t)r * kNC * kD;
        float bvv = 3.402823466e38f; int bii = 0x7fffffff;
#pragma unroll
        for (int q = 0; q < 4; q++) {
            const int c = cands[q];
            float s = 0.f;
#pragma unroll
            for (int u = 0; u < 16; u++) s = fmaf(x[u], C[(size_t)c * kD + u * 32 + lane], s);
#pragma unroll
            for (int m = 16; m >= 1; m >>= 1) s += __shfl_xor_sync(0xffffffffu, s, m);
            float v = g_cnorm[r * kNC + c] - 2.f * s;
            if (better(v, c, bvv, bii)) { bvv = v; bii = c; }
        }
        if (lane == 0) g_labels[r * kN + p] = bii;
    }
}

// ---------------- kernel 6a: point-centric partial sums (d-split) ------------
__global__ void __launch_bounds__(256) partial_kernel(const float* __restrict__ X)
{
    extern __shared__ float sm[];
    float* ssum = sm;
    int*   slab = (int*)(sm + kNC * 256);
    int*   scnt = (int*)(sm + kNC * 256) + kCHP;

    const int ch = blockIdx.x;
    const int r  = blockIdx.y >> 1, dh = blockIdx.y & 1;
    const int t = threadIdx.x;
    const int d = dh * 256 + t;
    const int p0 = ch * kCHP;
    const int* lab = g_labels + r * kN;

#pragma unroll
    for (int c = 0; c < kNC; c++) ssum[c * 256 + t] = 0.f;
    if (t < kNC) scnt[t] = 0;
    slab[t] = lab[p0 + t];
    __syncthreads();
    if (dh == 0) atomicAdd(&scnt[slab[t]], 1);
    __syncthreads();

    for (int i = 0; i < kCHP; i += 8) {
        float x0 = X[(size_t)(p0 + i + 0) * kD + d];
        float x1 = X[(size_t)(p0 + i + 1) * kD + d];
        float x2 = X[(size_t)(p0 + i + 2) * kD + d];
        float x3 = X[(size_t)(p0 + i + 3) * kD + d];
        float x4 = X[(size_t)(p0 + i + 4) * kD + d];
        float x5 = X[(size_t)(p0 + i + 5) * kD + d];
        float x6 = X[(size_t)(p0 + i + 6) * kD + d];
        float x7 = X[(size_t)(p0 + i + 7) * kD + d];
        int c0 = slab[i + 0], c1 = slab[i + 1], c2 = slab[i + 2], c3 = slab[i + 3];
        int c4 = slab[i + 4], c5 = slab[i + 5], c6 = slab[i + 6], c7 = slab[i + 7];
        ssum[c0 * 256 + t] += x0;
        ssum[c1 * 256 + t] += x1;
        ssum[c2 * 256 + t] += x2;
        ssum[c3 * 256 + t] += x3;
        ssum[c4 * 256 + t] += x4;
        ssum[c5 * 256 + t] += x5;
        ssum[c6 * 256 + t] += x6;
        ssum[c7 * 256 + t] += x7;
    }
    __syncthreads();

    const size_t base = (size_t)(r * kCH + ch) * kNC;
#pragma unroll
    for (int c = 0; c < kNC; c++)
        g_part[(base + c) * kD + d] = ssum[c * 256 + t];
    if (dh == 0 && t < kNC) g_pcnt[base + t] = scnt[t];
}

// ---------------- kernel 6b: combine partials -> centroid + norm -------------
__global__ void __launch_bounds__(512) combine_kernel()
{
    __shared__ float fred[16];
    const int c = blockIdx.x, r = blockIdx.y;
    const int t = threadIdx.x;
    const unsigned lane = t & 31;

    int cnt = 0;
    float sum = 0.f;
#pragma unroll
    for (int ch = 0; ch < kCH; ch++) {
        size_t base = (size_t)(r * kCH + ch) * kNC + c;
        cnt += g_pcnt[base];
        sum += g_part[base * kD + t];
    }
    const int rc = r * kNC + c;
    float oldc = g_cent[(size_t)rc * kD + t];
    float newc = (cnt > 0) ? (sum / (float)cnt) : oldc;
    g_cent[(size_t)rc * kD + t] = newc;

    float sq = newc * newc;
#pragma unroll
    for (int m = 16; m >= 1; m >>= 1) sq += __shfl_xor_sync(0xffffffffu, sq, m);
    if (lane == 0) fred[t >> 5] = sq;
    __syncthreads();
    if (t == 0) {
        float s = 0.f;
        for (int w = 0; w < 16; w++) s += fred[w];
        g_cnorm[rc] = s;
    }
}

// ---------------- kernel 7: scatter final output ----------------
__global__ void __launch_bounds__(256) scatter_kernel(
    const float* __restrict__ adj, float* __restrict__ out)
{
    int e = blockIdx.x * blockDim.x + threadIdx.x;
    int i = e >> 4;
    int j = g_knn[e];
    float v = adj[(size_t)i * kN + j];
    bool m = false;
#pragma unroll
    for (int r = 0; r < kNR; r++)
        m |= (g_labels[r * kN + i] == g_labels[r * kN + j]);
    out[(size_t)i * kN + j] = v + (m ? 1.f : 0.f);
}

// ---------------- launcher ----------------
extern "C" void kernel_launch(void* const* d_in, const int* in_sizes, int n_in,
                              void* d_out, int out_size)
{
    (void)in_sizes; (void)n_in; (void)out_size;
    const float* adj     = (const float*)d_in[0];
    const float* student = (const float*)d_in[1];
    const float* teacher = (const float*)d_in[2];
    float* out = (float*)d_out;

    constexpr size_t kPartSmem = (size_t)kNC * 256 * 4 + kCHP * 4 + kNC * 4;
    constexpr size_t kGemmSmem = 2 * (size_t)kGemmBufB;   // 73.7 KB
    constexpr size_t kAsgSmem  = 2 * (size_t)kAsgBufB;    // 55.3 KB
    static cudaStream_t s2 = nullptr, s1 = nullptr;
    static cudaEvent_t ev_fork = nullptr, ev_join = nullptr, ev_main = nullptr, ev_split = nullptr;
    if (!s2) {
        int lo, hi;
        cudaDeviceGetStreamPriorityRange(&lo, &hi);
        cudaStreamCreateWithPriority(&s2, cudaStreamNonBlocking, hi);
        cudaStreamCreateWithPriority(&s1, cudaStreamNonBlocking, lo);
        cudaEventCreateWithFlags(&ev_fork, cudaEventDisableTiming);
        cudaEventCreateWithFlags(&ev_join, cudaEventDisableTiming);
        cudaEventCreateWithFlags(&ev_main, cudaEventDisableTiming);
        cudaEventCreateWithFlags(&ev_split, cudaEventDisableTiming);
        cudaFuncSetAttribute(partial_kernel,
                             cudaFuncAttributeMaxDynamicSharedMemorySize, (int)kPartSmem);
        cudaFuncSetAttribute(gemm_hi_kernel,
                             cudaFuncAttributeMaxDynamicSharedMemorySize, (int)kGemmSmem);
        cudaFuncSetAttribute(assign_hi_kernel,
                             cudaFuncAttributeMaxDynamicSharedMemorySize, (int)kAsgSmem);
    }

    IdxArr ia;
    compute_init_indices(ia.v);

    cudaEventRecord(ev_fork, 0);
    cudaStreamWaitEvent(s2, ev_fork, 0);
    cudaStreamWaitEvent(s1, ev_fork, 0);

    // s1: tf32 hi split (Bhi also feeds assign on s2)
    split_hi_kernel<<<(kN * kD) / (256 * 4), 256, 0, s1>>>(student, teacher);
    cudaEventRecord(ev_split, s1);

    // s2: serial kmeans chain (hi tensor candidates + exact fp32 refine)
    gather_kernel<<<kRC, 128, 0, s2>>>(teacher, ia);
    cnorm_kernel<<<kRC, 128, 0, s2>>>();
    split_cent_hi_kernel<<<(kRC * kD) / (256 * 4), 256, 0, s2>>>();
    cudaStreamWaitEvent(s2, ev_split, 0);
    dim3 ga(kN / 128, kNR), gp(kCH, kNR * 2), gc(kNC, kNR);
    for (int it = 0; it < kIters; it++) {
        assign_hi_kernel<<<ga, 256, kAsgSmem, s2>>>();
        refine_kernel<<<kN / 8, 256, 0, s2>>>(teacher);
        partial_kernel<<<gp, 256, kPartSmem, s2>>>(teacher);
        combine_kernel<<<gc, 512, 0, s2>>>();
        split_cent_hi_kernel<<<(kRC * kD) / (256 * 4), 256, 0, s2>>>();
    }
    assign_hi_kernel<<<ga, 256, kAsgSmem, s2>>>();
    refine_kernel<<<kN / 8, 256, 0, s2>>>(teacher);
    cudaEventRecord(ev_join, s2);

    // s1: hi-only sim GEMM -> spill-free top-32 -> fp32 rescore -> zero out
    dim3 g1(kN / 128, kN / 128);
    gemm_hi_kernel<<<g1, 256, kGemmSmem, s1>>>(out);
    topk32_kernel<<<kN, 256, 0, s1>>>(out);
    rescore_kernel<<<kN, 256, 0, s1>>>(student, teacher);
    cudaMemsetAsync(d_out, 0, (size_t)kN * kN * sizeof(float), s1);
    cudaEventRecord(ev_main, s1);

    cudaStreamWaitEvent(0, ev_join, 0);
    cudaStreamWaitEvent(0, ev_main, 0);
    scatter_kernel<<<kN * kTK / 256, 256>>>(adj, out);
}